// round 2
// baseline (speedup 1.0000x reference)
#include <cuda_runtime.h>

#define N 4096
#define D 512
#define NCHUNK 16
#define RPC (N / NCHUNK)              /* 256 rows per column-chunk */
#define LA (-8.317766166719344f)      /* -ln(4096) */
#define LB (-8.317766166719344f)
#define THRESH (-25.0f)
#define THRESH_P (-40.0f)

/* ---- scratch (device globals: allocation-free rule) ---- */
__device__ float d_M[(size_t)N * N];          /* 64 MB cost matrix */
__device__ float d_f[N];
__device__ float d_g[N];
__device__ float d_x2[N];
__device__ float d_y2[N];
__device__ float d_cm[NCHUNK * N];            /* column partial max */
__device__ float d_cs[NCHUNK * N];            /* column partial sum */
__device__ float d_R[N];                      /* row sums of P */
__device__ float d_C[N];                      /* col sums of P */

/* ================= prep: squared norms + f=g=0 ================= */
__global__ void __launch_bounds__(256) prep_kernel(const float* __restrict__ x,
                                                   const float* __restrict__ y) {
    int warp = threadIdx.x >> 5, lane = threadIdx.x & 31;
    int id = blockIdx.x * 8 + warp;           /* 0..8191 */
    const float* src = (id < N) ? x : y;
    int row = (id < N) ? id : id - N;
    const float4* p = (const float4*)(src + (size_t)row * D);
    float s = 0.f;
#pragma unroll
    for (int k = 0; k < 4; ++k) {
        float4 v = p[lane + 32 * k];
        s += v.x * v.x + v.y * v.y + v.z * v.z + v.w * v.w;
    }
#pragma unroll
    for (int o = 16; o; o >>= 1) s += __shfl_xor_sync(0xffffffffu, s, o);
    if (lane == 0) {
        if (id < N) { d_x2[row] = s; d_f[row] = 0.f; }
        else        { d_y2[row] = s; d_g[row] = 0.f; }
    }
}

/* ================= M = max(x2 + y2 - 2 X Y^T, 0) ================= */
__global__ void __launch_bounds__(256) gemm_kernel(const float* __restrict__ X,
                                                   const float* __restrict__ Y) {
    __shared__ float As[16][132];
    __shared__ float Bs[16][132];
    int tid = threadIdx.x;
    int tx = tid & 15, ty = tid >> 4;
    int bm = blockIdx.y * 128, bn = blockIdx.x * 128;
    float acc[8][8];
#pragma unroll
    for (int i = 0; i < 8; ++i)
#pragma unroll
        for (int j = 0; j < 8; ++j) acc[i][j] = 0.f;

    for (int k0 = 0; k0 < D; k0 += 16) {
#pragma unroll
        for (int l = 0; l < 2; ++l) {
            int t2 = tid + l * 256;
            int r = t2 >> 2, c4 = t2 & 3;
            float4 a = *(const float4*)(X + (size_t)(bm + r) * D + k0 + c4 * 4);
            float4 b = *(const float4*)(Y + (size_t)(bn + r) * D + k0 + c4 * 4);
            As[c4 * 4 + 0][r] = a.x; As[c4 * 4 + 1][r] = a.y;
            As[c4 * 4 + 2][r] = a.z; As[c4 * 4 + 3][r] = a.w;
            Bs[c4 * 4 + 0][r] = b.x; Bs[c4 * 4 + 1][r] = b.y;
            Bs[c4 * 4 + 2][r] = b.z; Bs[c4 * 4 + 3][r] = b.w;
        }
        __syncthreads();
#pragma unroll
        for (int kk = 0; kk < 16; ++kk) {
            float a[8], b[8];
            *(float4*)(a)     = *(const float4*)&As[kk][ty * 8];
            *(float4*)(a + 4) = *(const float4*)&As[kk][ty * 8 + 4];
            *(float4*)(b)     = *(const float4*)&Bs[kk][tx * 8];
            *(float4*)(b + 4) = *(const float4*)&Bs[kk][tx * 8 + 4];
#pragma unroll
            for (int i = 0; i < 8; ++i)
#pragma unroll
                for (int j = 0; j < 8; ++j) acc[i][j] += a[i] * b[j];
        }
        __syncthreads();
    }

    float y2v[8];
#pragma unroll
    for (int j = 0; j < 8; ++j) y2v[j] = d_y2[bn + tx * 8 + j];
#pragma unroll
    for (int i = 0; i < 8; ++i) {
        int row = bm + ty * 8 + i;
        float x2r = d_x2[row];
        float out[8];
#pragma unroll
        for (int j = 0; j < 8; ++j)
            out[j] = fmaxf(x2r + y2v[j] - 2.f * acc[i][j], 0.f);
        *(float4*)(d_M + (size_t)row * N + bn + tx * 8)     = *(float4*)(out);
        *(float4*)(d_M + (size_t)row * N + bn + tx * 8 + 4) = *(float4*)(out + 4);
    }
}

/* ========== f[i] = LA - LSE_j(g[j] - M[i][j]); 8 rows/block ========== */
__global__ void __launch_bounds__(256) row_lse_kernel() {
    __shared__ float gs[N];
    __shared__ float redM[8];
    __shared__ float redS[8];
    int tid = threadIdx.x;
#pragma unroll
    for (int c = 0; c < 4; ++c)
        ((float4*)gs)[tid + c * 256] = ((const float4*)d_g)[tid + c * 256];
    __syncthreads();
    int warp = tid >> 5, lane = tid & 31;

    for (int r = 0; r < 8; ++r) {
        int row = blockIdx.x * 8 + r;
        const float4* Mr = (const float4*)(d_M + (size_t)row * N);
        float v[16];
        float lm = -1e30f;
#pragma unroll
        for (int c = 0; c < 4; ++c) {
            int idx = tid + c * 256;
            float4 mv = Mr[idx];
            float4 gv = ((const float4*)gs)[idx];
            v[c * 4 + 0] = gv.x - mv.x;
            v[c * 4 + 1] = gv.y - mv.y;
            v[c * 4 + 2] = gv.z - mv.z;
            v[c * 4 + 3] = gv.w - mv.w;
            lm = fmaxf(lm, fmaxf(fmaxf(v[c * 4], v[c * 4 + 1]),
                                 fmaxf(v[c * 4 + 2], v[c * 4 + 3])));
        }
#pragma unroll
        for (int o = 16; o; o >>= 1) lm = fmaxf(lm, __shfl_xor_sync(0xffffffffu, lm, o));
        if (lane == 0) redM[warp] = lm;
        __syncthreads();
        float m = redM[0];
#pragma unroll
        for (int k = 1; k < 8; ++k) m = fmaxf(m, redM[k]);

        float ls = 0.f;
#pragma unroll
        for (int k = 0; k < 16; ++k) {
            float dd = v[k] - m;
            if (dd > THRESH) ls += __expf(dd);
        }
#pragma unroll
        for (int o = 16; o; o >>= 1) ls += __shfl_xor_sync(0xffffffffu, ls, o);
        if (lane == 0) redS[warp] = ls;
        __syncthreads();
        if (tid == 0) {
            float s = redS[0];
#pragma unroll
            for (int k = 1; k < 8; ++k) s += redS[k];
            d_f[row] = LA - (m + __logf(s));
        }
        __syncthreads();
    }
}

/* ========== column LSE partials: thread-per-column, online max/sum ========== */
__device__ __forceinline__ void online_upd(float& m, float& s, float x) {
    if (x > m) { s = s * __expf(m - x) + 1.0f; m = x; }
    else if (x - m > THRESH) s += __expf(x - m);
}

__global__ void __launch_bounds__(256) col_lse_kernel() {
    __shared__ float fs[RPC];
    int tid = threadIdx.x;
    int chunk = blockIdx.y;
    int i0 = chunk * RPC;
    fs[tid] = d_f[i0 + tid];
    __syncthreads();
    int j = blockIdx.x * 256 + tid;
    const float* p = d_M + (size_t)i0 * N + j;
    float m0 = -1e30f, m1 = -1e30f, m2 = -1e30f, m3 = -1e30f;
    float s0 = 0.f, s1 = 0.f, s2 = 0.f, s3 = 0.f;

    float c0 = p[0], c1 = p[N], c2 = p[2 * N], c3 = p[3 * N];
    p += 4 * (size_t)N;
    for (int i = 0; i < RPC - 4; i += 4) {
        float n0 = p[0], n1 = p[N], n2 = p[2 * N], n3 = p[3 * N];
        p += 4 * (size_t)N;
        online_upd(m0, s0, fs[i + 0] - c0);
        online_upd(m1, s1, fs[i + 1] - c1);
        online_upd(m2, s2, fs[i + 2] - c2);
        online_upd(m3, s3, fs[i + 3] - c3);
        c0 = n0; c1 = n1; c2 = n2; c3 = n3;
    }
    online_upd(m0, s0, fs[RPC - 4] - c0);
    online_upd(m1, s1, fs[RPC - 3] - c1);
    online_upd(m2, s2, fs[RPC - 2] - c2);
    online_upd(m3, s3, fs[RPC - 1] - c3);

    /* merge 4 accumulators */
    if (m1 > m0) { s0 = s0 * __expf(m0 - m1) + s1; m0 = m1; }
    else if (m1 - m0 > THRESH) s0 += s1 * __expf(m1 - m0);
    if (m3 > m2) { s2 = s2 * __expf(m2 - m3) + s3; m2 = m3; }
    else if (m3 - m2 > THRESH) s2 += s3 * __expf(m3 - m2);
    if (m2 > m0) { s0 = s0 * __expf(m0 - m2) + s2; m0 = m2; }
    else if (m2 - m0 > THRESH) s0 += s2 * __expf(m2 - m0);

    d_cm[chunk * N + j] = m0;
    d_cs[chunk * N + j] = s0;
}

__global__ void __launch_bounds__(256) col_combine_kernel() {
    int j = blockIdx.x * 256 + threadIdx.x;
    float mm = -1e30f;
#pragma unroll
    for (int k = 0; k < NCHUNK; ++k) mm = fmaxf(mm, d_cm[k * N + j]);
    float ss = 0.f;
#pragma unroll
    for (int k = 0; k < NCHUNK; ++k) {
        float dd = d_cm[k * N + j] - mm;
        if (dd > THRESH) ss += d_cs[k * N + j] * __expf(dd);
    }
    d_g[j] = LB - (mm + __logf(ss));
}

/* ========== final: R_i = sum_j exp(f_i+g_j-M_ij) ========== */
__global__ void __launch_bounds__(256) row_psum_kernel() {
    __shared__ float gs[N];
    __shared__ float redS[8];
    int tid = threadIdx.x;
#pragma unroll
    for (int c = 0; c < 4; ++c)
        ((float4*)gs)[tid + c * 256] = ((const float4*)d_g)[tid + c * 256];
    __syncthreads();
    int warp = tid >> 5, lane = tid & 31;

    for (int r = 0; r < 8; ++r) {
        int row = blockIdx.x * 8 + r;
        float fr = d_f[row];
        const float4* Mr = (const float4*)(d_M + (size_t)row * N);
        float ls = 0.f;
#pragma unroll
        for (int c = 0; c < 4; ++c) {
            int idx = tid + c * 256;
            float4 mv = Mr[idx];
            float4 gv = ((const float4*)gs)[idx];
            float t0 = fr + gv.x - mv.x;
            float t1 = fr + gv.y - mv.y;
            float t2 = fr + gv.z - mv.z;
            float t3 = fr + gv.w - mv.w;
            if (t0 > THRESH_P) ls += __expf(t0);
            if (t1 > THRESH_P) ls += __expf(t1);
            if (t2 > THRESH_P) ls += __expf(t2);
            if (t3 > THRESH_P) ls += __expf(t3);
        }
#pragma unroll
        for (int o = 16; o; o >>= 1) ls += __shfl_xor_sync(0xffffffffu, ls, o);
        if (lane == 0) redS[warp] = ls;
        __syncthreads();
        if (tid == 0) {
            float s = redS[0];
#pragma unroll
            for (int k = 1; k < 8; ++k) s += redS[k];
            d_R[row] = s;
        }
        __syncthreads();
    }
}

/* C_j = sum_i exp(f_i+g_j-M_ij): partials then combine */
__global__ void __launch_bounds__(256) col_psum_kernel() {
    __shared__ float fs[RPC];
    int tid = threadIdx.x;
    int chunk = blockIdx.y;
    int i0 = chunk * RPC;
    fs[tid] = d_f[i0 + tid];
    __syncthreads();
    int j = blockIdx.x * 256 + tid;
    float gj = d_g[j];
    const float* p = d_M + (size_t)i0 * N + j;
    float s0 = 0.f, s1 = 0.f, s2 = 0.f, s3 = 0.f;

    float c0 = p[0], c1 = p[N], c2 = p[2 * N], c3 = p[3 * N];
    p += 4 * (size_t)N;
    for (int i = 0; i < RPC - 4; i += 4) {
        float n0 = p[0], n1 = p[N], n2 = p[2 * N], n3 = p[3 * N];
        p += 4 * (size_t)N;
        float t0 = fs[i + 0] + gj - c0; if (t0 > THRESH_P) s0 += __expf(t0);
        float t1 = fs[i + 1] + gj - c1; if (t1 > THRESH_P) s1 += __expf(t1);
        float t2 = fs[i + 2] + gj - c2; if (t2 > THRESH_P) s2 += __expf(t2);
        float t3 = fs[i + 3] + gj - c3; if (t3 > THRESH_P) s3 += __expf(t3);
        c0 = n0; c1 = n1; c2 = n2; c3 = n3;
    }
    { float t = fs[RPC - 4] + gj - c0; if (t > THRESH_P) s0 += __expf(t); }
    { float t = fs[RPC - 3] + gj - c1; if (t > THRESH_P) s1 += __expf(t); }
    { float t = fs[RPC - 2] + gj - c2; if (t > THRESH_P) s2 += __expf(t); }
    { float t = fs[RPC - 1] + gj - c3; if (t > THRESH_P) s3 += __expf(t); }

    d_cs[chunk * N + j] = (s0 + s1) + (s2 + s3);
}

__global__ void __launch_bounds__(256) col_psum_combine_kernel() {
    int j = blockIdx.x * 256 + threadIdx.x;
    float ss = 0.f;
#pragma unroll
    for (int k = 0; k < NCHUNK; ++k) ss += d_cs[k * N + j];
    d_C[j] = ss;
}

/* loss = sum_i f_i R_i + sum_j g_j C_j - (la+lb+1) * sum R + 1 */
__global__ void __launch_bounds__(256) final_kernel(float* __restrict__ out) {
    int tid = threadIdx.x;
    double acc = 0.0;
    const double k = (double)LA + (double)LB + 1.0;
    for (int i = tid; i < N; i += 256) {
        double Ri = (double)d_R[i];
        acc += (double)d_f[i] * Ri + (double)d_g[i] * (double)d_C[i] - k * Ri;
    }
    __shared__ double red[256];
    red[tid] = acc;
    __syncthreads();
    for (int o = 128; o; o >>= 1) {
        if (tid < o) red[tid] += red[tid + o];
        __syncthreads();
    }
    if (tid == 0) out[0] = (float)(red[0] + 1.0);
}

/* ================================================================= */
extern "C" void kernel_launch(void* const* d_in, const int* in_sizes, int n_in,
                              void* d_out, int out_size) {
    (void)in_sizes; (void)n_in; (void)out_size;
    const float* x = (const float*)d_in[0];
    const float* y = (const float*)d_in[1];
    float* out = (float*)d_out;

    prep_kernel<<<1024, 256>>>(x, y);
    gemm_kernel<<<dim3(32, 32), 256>>>(x, y);

    for (int it = 0; it < 100; ++it) {
        row_lse_kernel<<<512, 256>>>();
        col_lse_kernel<<<dim3(16, NCHUNK), 256>>>();
        col_combine_kernel<<<16, 256>>>();
    }

    row_psum_kernel<<<512, 256>>>();
    col_psum_kernel<<<dim3(16, NCHUNK), 256>>>();
    col_psum_combine_kernel<<<16, 256>>>();
    final_kernel<<<1, 256>>>(out);
}

// round 3
// speedup vs baseline: 1.3731x; 1.3731x over previous
#include <cuda_runtime.h>

#define N 4096
#define D 512
#define LA (-8.317766166719344f)      /* -ln(4096) */
#define LB (-8.317766166719344f)
#define THRESH (-25.0f)
#define THRESH_P (-40.0f)

/* ---- scratch (device globals: allocation-free rule) ---- */
__device__ float d_M [(size_t)N * N];         /* 64 MB cost matrix          */
__device__ float d_Mt[(size_t)N * N];         /* 64 MB transposed copy      */
__device__ float d_f[N];
__device__ float d_g[N];
__device__ float d_x2[N];
__device__ float d_y2[N];
__device__ float d_R[N];                      /* row sums of P */
__device__ float d_C[N];                      /* col sums of P */

/* ================= prep: squared norms + f=g=0 ================= */
__global__ void __launch_bounds__(256) prep_kernel(const float* __restrict__ x,
                                                   const float* __restrict__ y) {
    int warp = threadIdx.x >> 5, lane = threadIdx.x & 31;
    int id = blockIdx.x * 8 + warp;           /* 0..8191 */
    const float* src = (id < N) ? x : y;
    int row = (id < N) ? id : id - N;
    const float4* p = (const float4*)(src + (size_t)row * D);
    float s = 0.f;
#pragma unroll
    for (int k = 0; k < 4; ++k) {
        float4 v = p[lane + 32 * k];
        s += v.x * v.x + v.y * v.y + v.z * v.z + v.w * v.w;
    }
#pragma unroll
    for (int o = 16; o; o >>= 1) s += __shfl_xor_sync(0xffffffffu, s, o);
    if (lane == 0) {
        if (id < N) { d_x2[row] = s; d_f[row] = 0.f; }
        else        { d_y2[row] = s; d_g[row] = 0.f; }
    }
}

/* ============ M = max(x2 + y2 - 2 X Y^T, 0); also writes M^T ============ */
__global__ void __launch_bounds__(256) gemm_kernel(const float* __restrict__ X,
                                                   const float* __restrict__ Y) {
    __shared__ float As[16][132];
    __shared__ float Bs[16][132];
    int tid = threadIdx.x;
    int tx = tid & 15, ty = tid >> 4;
    int bm = blockIdx.y * 128, bn = blockIdx.x * 128;
    float acc[8][8];
#pragma unroll
    for (int i = 0; i < 8; ++i)
#pragma unroll
        for (int j = 0; j < 8; ++j) acc[i][j] = 0.f;

    for (int k0 = 0; k0 < D; k0 += 16) {
#pragma unroll
        for (int l = 0; l < 2; ++l) {
            int t2 = tid + l * 256;
            int r = t2 >> 2, c4 = t2 & 3;
            float4 a = *(const float4*)(X + (size_t)(bm + r) * D + k0 + c4 * 4);
            float4 b = *(const float4*)(Y + (size_t)(bn + r) * D + k0 + c4 * 4);
            As[c4 * 4 + 0][r] = a.x; As[c4 * 4 + 1][r] = a.y;
            As[c4 * 4 + 2][r] = a.z; As[c4 * 4 + 3][r] = a.w;
            Bs[c4 * 4 + 0][r] = b.x; Bs[c4 * 4 + 1][r] = b.y;
            Bs[c4 * 4 + 2][r] = b.z; Bs[c4 * 4 + 3][r] = b.w;
        }
        __syncthreads();
#pragma unroll
        for (int kk = 0; kk < 16; ++kk) {
            float a[8], b[8];
            *(float4*)(a)     = *(const float4*)&As[kk][ty * 8];
            *(float4*)(a + 4) = *(const float4*)&As[kk][ty * 8 + 4];
            *(float4*)(b)     = *(const float4*)&Bs[kk][tx * 8];
            *(float4*)(b + 4) = *(const float4*)&Bs[kk][tx * 8 + 4];
#pragma unroll
            for (int i = 0; i < 8; ++i)
#pragma unroll
                for (int j = 0; j < 8; ++j) acc[i][j] += a[i] * b[j];
        }
        __syncthreads();
    }

    float y2v[8];
#pragma unroll
    for (int j = 0; j < 8; ++j) y2v[j] = d_y2[bn + tx * 8 + j];
    float x2v[8];
#pragma unroll
    for (int i = 0; i < 8; ++i) x2v[i] = d_x2[bm + ty * 8 + i];

#pragma unroll
    for (int i = 0; i < 8; ++i)
#pragma unroll
        for (int j = 0; j < 8; ++j)
            acc[i][j] = fmaxf(x2v[i] + y2v[j] - 2.f * acc[i][j], 0.f);

    /* M */
#pragma unroll
    for (int i = 0; i < 8; ++i) {
        int row = bm + ty * 8 + i;
        float out[8];
#pragma unroll
        for (int j = 0; j < 8; ++j) out[j] = acc[i][j];
        *(float4*)(d_M + (size_t)row * N + bn + tx * 8)     = *(float4*)(out);
        *(float4*)(d_M + (size_t)row * N + bn + tx * 8 + 4) = *(float4*)(out + 4);
    }
    /* M^T */
#pragma unroll
    for (int j = 0; j < 8; ++j) {
        int trow = bn + tx * 8 + j;
        float out[8];
#pragma unroll
        for (int i = 0; i < 8; ++i) out[i] = acc[i][j];
        *(float4*)(d_Mt + (size_t)trow * N + bm + ty * 8)     = *(float4*)(out);
        *(float4*)(d_Mt + (size_t)trow * N + bm + ty * 8 + 4) = *(float4*)(out + 4);
    }
}

/* ========== out[row] = LOGW - LSE_j(vec[j] - Mat[row][j]); 8 rows/block ==========
   f-update: Mat=M,  vec=g, out=f
   g-update: Mat=Mt, vec=f, out=g                                                  */
__global__ void __launch_bounds__(256) lse_kernel(const float* __restrict__ Mat,
                                                  const float* __restrict__ vec,
                                                  float* __restrict__ outv,
                                                  float logw) {
    __shared__ float gs[N];
    __shared__ float redM[8];
    __shared__ float redS[8];
    int tid = threadIdx.x;
#pragma unroll
    for (int c = 0; c < 4; ++c)
        ((float4*)gs)[tid + c * 256] = ((const float4*)vec)[tid + c * 256];
    __syncthreads();
    int warp = tid >> 5, lane = tid & 31;

    for (int r = 0; r < 8; ++r) {
        int row = blockIdx.x * 8 + r;
        const float4* Mr = (const float4*)(Mat + (size_t)row * N);
        float v[16];
        float lm = -1e30f;
#pragma unroll
        for (int c = 0; c < 4; ++c) {
            int idx = tid + c * 256;
            float4 mv = Mr[idx];
            float4 gv = ((const float4*)gs)[idx];
            v[c * 4 + 0] = gv.x - mv.x;
            v[c * 4 + 1] = gv.y - mv.y;
            v[c * 4 + 2] = gv.z - mv.z;
            v[c * 4 + 3] = gv.w - mv.w;
            lm = fmaxf(lm, fmaxf(fmaxf(v[c * 4], v[c * 4 + 1]),
                                 fmaxf(v[c * 4 + 2], v[c * 4 + 3])));
        }
#pragma unroll
        for (int o = 16; o; o >>= 1) lm = fmaxf(lm, __shfl_xor_sync(0xffffffffu, lm, o));
        if (lane == 0) redM[warp] = lm;
        __syncthreads();
        float m = redM[0];
#pragma unroll
        for (int k = 1; k < 8; ++k) m = fmaxf(m, redM[k]);

        float ls = 0.f;
#pragma unroll
        for (int k = 0; k < 16; ++k) {
            float dd = v[k] - m;
            if (dd > THRESH) ls += __expf(dd);
        }
#pragma unroll
        for (int o = 16; o; o >>= 1) ls += __shfl_xor_sync(0xffffffffu, ls, o);
        if (lane == 0) redS[warp] = ls;
        __syncthreads();
        if (tid == 0) {
            float s = redS[0];
#pragma unroll
            for (int k = 1; k < 8; ++k) s += redS[k];
            outv[row] = logw - (m + __logf(s));
        }
        __syncthreads();
    }
}

/* ========== out[row] = sum_j exp(scal[row] + vec[j] - Mat[row][j]) ==========
   R: Mat=M,  vec=g, scal=f ;  C: Mat=Mt, vec=f, scal=g                        */
__global__ void __launch_bounds__(256) psum_kernel(const float* __restrict__ Mat,
                                                   const float* __restrict__ vec,
                                                   const float* __restrict__ scal,
                                                   float* __restrict__ outv) {
    __shared__ float gs[N];
    __shared__ float redS[8];
    int tid = threadIdx.x;
#pragma unroll
    for (int c = 0; c < 4; ++c)
        ((float4*)gs)[tid + c * 256] = ((const float4*)vec)[tid + c * 256];
    __syncthreads();
    int warp = tid >> 5, lane = tid & 31;

    for (int r = 0; r < 8; ++r) {
        int row = blockIdx.x * 8 + r;
        float fr = scal[row];
        const float4* Mr = (const float4*)(Mat + (size_t)row * N);
        float ls = 0.f;
#pragma unroll
        for (int c = 0; c < 4; ++c) {
            int idx = tid + c * 256;
            float4 mv = Mr[idx];
            float4 gv = ((const float4*)gs)[idx];
            float t0 = fr + gv.x - mv.x;
            float t1 = fr + gv.y - mv.y;
            float t2 = fr + gv.z - mv.z;
            float t3 = fr + gv.w - mv.w;
            if (t0 > THRESH_P) ls += __expf(t0);
            if (t1 > THRESH_P) ls += __expf(t1);
            if (t2 > THRESH_P) ls += __expf(t2);
            if (t3 > THRESH_P) ls += __expf(t3);
        }
#pragma unroll
        for (int o = 16; o; o >>= 1) ls += __shfl_xor_sync(0xffffffffu, ls, o);
        if (lane == 0) redS[warp] = ls;
        __syncthreads();
        if (tid == 0) {
            float s = redS[0];
#pragma unroll
            for (int k = 1; k < 8; ++k) s += redS[k];
            outv[row] = s;
        }
        __syncthreads();
    }
}

/* loss = sum_i f_i R_i + sum_j g_j C_j - (la+lb+1) * sum R + 1 */
__global__ void __launch_bounds__(256) final_kernel(float* __restrict__ out) {
    int tid = threadIdx.x;
    double acc = 0.0;
    const double k = (double)LA + (double)LB + 1.0;
    for (int i = tid; i < N; i += 256) {
        double Ri = (double)d_R[i];
        acc += (double)d_f[i] * Ri + (double)d_g[i] * (double)d_C[i] - k * Ri;
    }
    __shared__ double red[256];
    red[tid] = acc;
    __syncthreads();
    for (int o = 128; o; o >>= 1) {
        if (tid < o) red[tid] += red[tid + o];
        __syncthreads();
    }
    if (tid == 0) out[0] = (float)(red[0] + 1.0);
}

/* ================================================================= */
extern "C" void kernel_launch(void* const* d_in, const int* in_sizes, int n_in,
                              void* d_out, int out_size) {
    (void)in_sizes; (void)n_in; (void)out_size;
    const float* x = (const float*)d_in[0];
    const float* y = (const float*)d_in[1];
    float* out = (float*)d_out;

    /* resolve device-global addresses host-side once per launch */
    float *pM, *pMt, *pf, *pg, *pR, *pC;
    cudaGetSymbolAddress((void**)&pM,  d_M);
    cudaGetSymbolAddress((void**)&pMt, d_Mt);
    cudaGetSymbolAddress((void**)&pf,  d_f);
    cudaGetSymbolAddress((void**)&pg,  d_g);
    cudaGetSymbolAddress((void**)&pR,  d_R);
    cudaGetSymbolAddress((void**)&pC,  d_C);

    prep_kernel<<<1024, 256>>>(x, y);
    gemm_kernel<<<dim3(32, 32), 256>>>(x, y);

    for (int it = 0; it < 100; ++it) {
        lse_kernel<<<512, 256>>>(pM,  pg, pf, LA);   /* f update  */
        lse_kernel<<<512, 256>>>(pMt, pf, pg, LB);   /* g update  */
    }

    psum_kernel<<<512, 256>>>(pM,  pg, pf, pR);
    psum_kernel<<<512, 256>>>(pMt, pf, pg, pC);
    final_kernel<<<1, 256>>>(out);
}

// round 4
// speedup vs baseline: 1.6934x; 1.2333x over previous
#include <cuda_runtime.h>
#include <cuda_bf16.h>

#define N 4096
#define D 512
#define LA (-8.317766166719344f)      /* -ln(4096) */
#define LB (-8.317766166719344f)
#define THRESH (-25.0f)
#define THRESH_P (-40.0f)
#define RPB 4                          /* rows per block in LSE/psum */

/* ---- scratch (device globals: allocation-free rule) ----
   S  = 2 * X Y^T   (bf16, 33.5 MB)
   St = S^T         (bf16, 33.5 MB)   -> both L2-resident (126 MB L2)      */
__device__ __nv_bfloat162 d_S [(size_t)N * N / 2];
__device__ __nv_bfloat162 d_St[(size_t)N * N / 2];
__device__ float d_fh[N];              /* f - x2 */
__device__ float d_gh[N];              /* g - y2 */
__device__ float d_x2[N];
__device__ float d_y2[N];
__device__ float d_R[N];               /* row sums of P */
__device__ float d_C[N];               /* col sums of P */

/* ================= prep: squared norms + fh=-x2, gh=-y2 ================= */
__global__ void __launch_bounds__(256) prep_kernel(const float* __restrict__ x,
                                                   const float* __restrict__ y) {
    int warp = threadIdx.x >> 5, lane = threadIdx.x & 31;
    int id = blockIdx.x * 8 + warp;           /* 0..8191 */
    const float* src = (id < N) ? x : y;
    int row = (id < N) ? id : id - N;
    const float4* p = (const float4*)(src + (size_t)row * D);
    float s = 0.f;
#pragma unroll
    for (int k = 0; k < 4; ++k) {
        float4 v = p[lane + 32 * k];
        s += v.x * v.x + v.y * v.y + v.z * v.z + v.w * v.w;
    }
#pragma unroll
    for (int o = 16; o; o >>= 1) s += __shfl_xor_sync(0xffffffffu, s, o);
    if (lane == 0) {
        if (id < N) { d_x2[row] = s; d_fh[row] = -s; }
        else        { d_y2[row] = s; d_gh[row] = -s; }
    }
}

/* ============ S = 2 X Y^T (bf16), also writes S^T ============ */
__global__ void __launch_bounds__(256) gemm_kernel(const float* __restrict__ X,
                                                   const float* __restrict__ Y) {
    __shared__ float As[16][132];
    __shared__ float Bs[16][132];
    int tid = threadIdx.x;
    int tx = tid & 15, ty = tid >> 4;
    int bm = blockIdx.y * 128, bn = blockIdx.x * 128;
    float acc[8][8];
#pragma unroll
    for (int i = 0; i < 8; ++i)
#pragma unroll
        for (int j = 0; j < 8; ++j) acc[i][j] = 0.f;

    for (int k0 = 0; k0 < D; k0 += 16) {
#pragma unroll
        for (int l = 0; l < 2; ++l) {
            int t2 = tid + l * 256;
            int r = t2 >> 2, c4 = t2 & 3;
            float4 a = *(const float4*)(X + (size_t)(bm + r) * D + k0 + c4 * 4);
            float4 b = *(const float4*)(Y + (size_t)(bn + r) * D + k0 + c4 * 4);
            As[c4 * 4 + 0][r] = a.x; As[c4 * 4 + 1][r] = a.y;
            As[c4 * 4 + 2][r] = a.z; As[c4 * 4 + 3][r] = a.w;
            Bs[c4 * 4 + 0][r] = b.x; Bs[c4 * 4 + 1][r] = b.y;
            Bs[c4 * 4 + 2][r] = b.z; Bs[c4 * 4 + 3][r] = b.w;
        }
        __syncthreads();
#pragma unroll
        for (int kk = 0; kk < 16; ++kk) {
            float a[8], b[8];
            *(float4*)(a)     = *(const float4*)&As[kk][ty * 8];
            *(float4*)(a + 4) = *(const float4*)&As[kk][ty * 8 + 4];
            *(float4*)(b)     = *(const float4*)&Bs[kk][tx * 8];
            *(float4*)(b + 4) = *(const float4*)&Bs[kk][tx * 8 + 4];
#pragma unroll
            for (int i = 0; i < 8; ++i)
#pragma unroll
                for (int j = 0; j < 8; ++j) acc[i][j] += a[i] * b[j];
        }
        __syncthreads();
    }

    /* S rows: row = bm+ty*8+i, cols bn+tx*8 .. +7  (8 bf16 = one uint4) */
#pragma unroll
    for (int i = 0; i < 8; ++i) {
        int row = bm + ty * 8 + i;
        __nv_bfloat162 pk[4];
#pragma unroll
        for (int k = 0; k < 4; ++k)
            pk[k] = __floats2bfloat162_rn(2.f * acc[i][2 * k], 2.f * acc[i][2 * k + 1]);
        *(uint4*)(d_S + (size_t)row * (N / 2) + (bn + tx * 8) / 2) = *(uint4*)pk;
    }
    /* S^T rows: trow = bn+tx*8+j, cols bm+ty*8 .. +7 */
#pragma unroll
    for (int j = 0; j < 8; ++j) {
        int trow = bn + tx * 8 + j;
        __nv_bfloat162 pk[4];
#pragma unroll
        for (int k = 0; k < 4; ++k)
            pk[k] = __floats2bfloat162_rn(2.f * acc[2 * k][j], 2.f * acc[2 * k + 1][j]);
        *(uint4*)(d_St + (size_t)trow * (N / 2) + (bm + ty * 8) / 2) = *(uint4*)pk;
    }
}

__device__ __forceinline__ void unpack8(uint4 u, float* v) {
    v[0] = __uint_as_float(u.x << 16);
    v[1] = __uint_as_float(u.x & 0xFFFF0000u);
    v[2] = __uint_as_float(u.y << 16);
    v[3] = __uint_as_float(u.y & 0xFFFF0000u);
    v[4] = __uint_as_float(u.z << 16);
    v[5] = __uint_as_float(u.z & 0xFFFF0000u);
    v[6] = __uint_as_float(u.w << 16);
    v[7] = __uint_as_float(u.w & 0xFFFF0000u);
}

/* ======= out_h[row] = logw - LSE_j(vec_h[j] + S[row][j]); RPB rows/block ======= */
__global__ void __launch_bounds__(256) lse_kernel(const uint4* __restrict__ S,
                                                  const float* __restrict__ vh,
                                                  float* __restrict__ outh,
                                                  float logw) {
    __shared__ float gs[N];
    __shared__ float redM[8];
    __shared__ float redS[8];
    int tid = threadIdx.x;
#pragma unroll
    for (int c = 0; c < 4; ++c)
        ((float4*)gs)[tid + c * 256] = ((const float4*)vh)[tid + c * 256];
    __syncthreads();
    int warp = tid >> 5, lane = tid & 31;

    for (int r = 0; r < RPB; ++r) {
        int row = blockIdx.x * RPB + r;
        const uint4* Sr = S + (size_t)row * (N / 8);
        float v[16];
        float lm = -1e30f;
#pragma unroll
        for (int c = 0; c < 2; ++c) {
            int idx = tid + c * 256;              /* uint4 index: 8 elems */
            uint4 u = Sr[idx];
            float sv[8];
            unpack8(u, sv);
            float4 gA = ((const float4*)gs)[2 * idx];
            float4 gB = ((const float4*)gs)[2 * idx + 1];
            float* vv = v + c * 8;
            vv[0] = gA.x + sv[0]; vv[1] = gA.y + sv[1];
            vv[2] = gA.z + sv[2]; vv[3] = gA.w + sv[3];
            vv[4] = gB.x + sv[4]; vv[5] = gB.y + sv[5];
            vv[6] = gB.z + sv[6]; vv[7] = gB.w + sv[7];
#pragma unroll
            for (int k = 0; k < 8; k += 4)
                lm = fmaxf(lm, fmaxf(fmaxf(vv[k], vv[k + 1]),
                                     fmaxf(vv[k + 2], vv[k + 3])));
        }
#pragma unroll
        for (int o = 16; o; o >>= 1) lm = fmaxf(lm, __shfl_xor_sync(0xffffffffu, lm, o));
        if (lane == 0) redM[warp] = lm;
        __syncthreads();
        float m = redM[0];
#pragma unroll
        for (int k = 1; k < 8; ++k) m = fmaxf(m, redM[k]);

        float ls = 0.f;
#pragma unroll
        for (int k = 0; k < 16; ++k) {
            float dd = v[k] - m;
            if (dd > THRESH) ls += __expf(dd);
        }
#pragma unroll
        for (int o = 16; o; o >>= 1) ls += __shfl_xor_sync(0xffffffffu, ls, o);
        if (lane == 0) redS[warp] = ls;
        __syncthreads();
        if (tid == 0) {
            float s = redS[0];
#pragma unroll
            for (int k = 1; k < 8; ++k) s += redS[k];
            outh[row] = logw - (m + __logf(s));
        }
        __syncthreads();
    }
}

/* ======= out[row] = sum_j exp(scal_h[row] + vec_h[j] + S[row][j]) ======= */
__global__ void __launch_bounds__(256) psum_kernel(const uint4* __restrict__ S,
                                                   const float* __restrict__ vh,
                                                   const float* __restrict__ scalh,
                                                   float* __restrict__ outv) {
    __shared__ float gs[N];
    __shared__ float redS[8];
    int tid = threadIdx.x;
#pragma unroll
    for (int c = 0; c < 4; ++c)
        ((float4*)gs)[tid + c * 256] = ((const float4*)vh)[tid + c * 256];
    __syncthreads();
    int warp = tid >> 5, lane = tid & 31;

    for (int r = 0; r < RPB; ++r) {
        int row = blockIdx.x * RPB + r;
        float fr = scalh[row];
        const uint4* Sr = S + (size_t)row * (N / 8);
        float ls = 0.f;
#pragma unroll
        for (int c = 0; c < 2; ++c) {
            int idx = tid + c * 256;
            uint4 u = Sr[idx];
            float sv[8];
            unpack8(u, sv);
            float4 gA = ((const float4*)gs)[2 * idx];
            float4 gB = ((const float4*)gs)[2 * idx + 1];
            float t[8];
            t[0] = fr + gA.x + sv[0]; t[1] = fr + gA.y + sv[1];
            t[2] = fr + gA.z + sv[2]; t[3] = fr + gA.w + sv[3];
            t[4] = fr + gB.x + sv[4]; t[5] = fr + gB.y + sv[5];
            t[6] = fr + gB.z + sv[6]; t[7] = fr + gB.w + sv[7];
#pragma unroll
            for (int k = 0; k < 8; ++k)
                if (t[k] > THRESH_P) ls += __expf(t[k]);
        }
#pragma unroll
        for (int o = 16; o; o >>= 1) ls += __shfl_xor_sync(0xffffffffu, ls, o);
        if (lane == 0) redS[warp] = ls;
        __syncthreads();
        if (tid == 0) {
            float s = redS[0];
#pragma unroll
            for (int k = 1; k < 8; ++k) s += redS[k];
            outv[row] = s;
        }
        __syncthreads();
    }
}

/* loss = sum_i f_i R_i + sum_j g_j C_j - (la+lb+1) * sum R + 1
   with f = fh + x2, g = gh + y2                                          */
__global__ void __launch_bounds__(256) final_kernel(float* __restrict__ out) {
    int tid = threadIdx.x;
    double acc = 0.0;
    const double k = (double)LA + (double)LB + 1.0;
    for (int i = tid; i < N; i += 256) {
        double Ri = (double)d_R[i];
        double fi = (double)d_fh[i] + (double)d_x2[i];
        double gi = (double)d_gh[i] + (double)d_y2[i];
        acc += fi * Ri + gi * (double)d_C[i] - k * Ri;
    }
    __shared__ double red[256];
    red[tid] = acc;
    __syncthreads();
    for (int o = 128; o; o >>= 1) {
        if (tid < o) red[tid] += red[tid + o];
        __syncthreads();
    }
    if (tid == 0) out[0] = (float)(red[0] + 1.0);
}

/* ================================================================= */
extern "C" void kernel_launch(void* const* d_in, const int* in_sizes, int n_in,
                              void* d_out, int out_size) {
    (void)in_sizes; (void)n_in; (void)out_size;
    const float* x = (const float*)d_in[0];
    const float* y = (const float*)d_in[1];
    float* out = (float*)d_out;

    void *pS_, *pSt_, *pfh_, *pgh_, *pR_, *pC_;
    cudaGetSymbolAddress(&pS_,  d_S);
    cudaGetSymbolAddress(&pSt_, d_St);
    cudaGetSymbolAddress(&pfh_, d_fh);
    cudaGetSymbolAddress(&pgh_, d_gh);
    cudaGetSymbolAddress(&pR_,  d_R);
    cudaGetSymbolAddress(&pC_,  d_C);
    const uint4* pS  = (const uint4*)pS_;
    const uint4* pSt = (const uint4*)pSt_;
    float* pfh = (float*)pfh_;
    float* pgh = (float*)pgh_;
    float* pR  = (float*)pR_;
    float* pC  = (float*)pC_;

    prep_kernel<<<1024, 256>>>(x, y);
    gemm_kernel<<<dim3(32, 32), 256>>>(x, y);

    for (int it = 0; it < 100; ++it) {
        lse_kernel<<<N / RPB, 256>>>(pS,  pgh, pfh, LA);   /* fh update */
        lse_kernel<<<N / RPB, 256>>>(pSt, pfh, pgh, LB);   /* gh update */
    }

    psum_kernel<<<N / RPB, 256>>>(pS,  pgh, pfh, pR);
    psum_kernel<<<N / RPB, 256>>>(pSt, pfh, pgh, pC);
    final_kernel<<<1, 256>>>(out);
}

// round 7
// speedup vs baseline: 2.2045x; 1.3018x over previous
#include <cuda_runtime.h>
#include <cuda_bf16.h>

#define N 4096
#define D 512
#define LA (-8.317766166719344f)      /* -ln(4096) */
#define LB (-8.317766166719344f)
#define THRESH (-25.0f)
#define THRESH_P (-40.0f)
#define RPB 4                          /* rows per block in exact LSE/psum */
#define N_EXACT 4                      /* exact Sinkhorn iters before fast path */

/* ---- scratch (device globals: allocation-free rule) ----
   S  = 2 * X Y^T   (bf16, 33.5 MB)
   St = S^T         (bf16, 33.5 MB)   -> both L2-resident (126 MB L2)      */
__device__ __nv_bfloat162 d_S [(size_t)N * N / 2];
__device__ __nv_bfloat162 d_St[(size_t)N * N / 2];
__device__ float d_fh[N];              /* f - x2 */
__device__ float d_gh[N];              /* g - y2 */
__device__ float d_x2[N];
__device__ float d_y2[N];
__device__ float d_mf[N];              /* carried row-max shift for f pass */
__device__ float d_mg[N];              /* carried row-max shift for g pass */
__device__ float d_R[N];               /* row sums of P */
__device__ float d_C[N];               /* col sums of P */

/* ================= prep: squared norms + fh=-x2, gh=-y2 ================= */
__global__ void __launch_bounds__(256) prep_kernel(const float* __restrict__ x,
                                                   const float* __restrict__ y) {
    int warp = threadIdx.x >> 5, lane = threadIdx.x & 31;
    int id = blockIdx.x * 8 + warp;           /* 0..8191 */
    const float* src = (id < N) ? x : y;
    int row = (id < N) ? id : id - N;
    const float4* p = (const float4*)(src + (size_t)row * D);
    float s = 0.f;
#pragma unroll
    for (int k = 0; k < 4; ++k) {
        float4 v = p[lane + 32 * k];
        s += v.x * v.x + v.y * v.y + v.z * v.z + v.w * v.w;
    }
#pragma unroll
    for (int o = 16; o; o >>= 1) s += __shfl_xor_sync(0xffffffffu, s, o);
    if (lane == 0) {
        if (id < N) { d_x2[row] = s; d_fh[row] = -s; }
        else        { d_y2[row] = s; d_gh[row] = -s; }
    }
}

/* ============ S = 2 X Y^T (bf16), also writes S^T ============ */
__global__ void __launch_bounds__(256) gemm_kernel(const float* __restrict__ X,
                                                   const float* __restrict__ Y) {
    __shared__ float As[16][132];
    __shared__ float Bs[16][132];
    int tid = threadIdx.x;
    int tx = tid & 15, ty = tid >> 4;
    int bm = blockIdx.y * 128, bn = blockIdx.x * 128;
    float acc[8][8];
#pragma unroll
    for (int i = 0; i < 8; ++i)
#pragma unroll
        for (int j = 0; j < 8; ++j) acc[i][j] = 0.f;

    for (int k0 = 0; k0 < D; k0 += 16) {
#pragma unroll
        for (int l = 0; l < 2; ++l) {
            int t2 = tid + l * 256;
            int r = t2 >> 2, c4 = t2 & 3;
            float4 a = *(const float4*)(X + (size_t)(bm + r) * D + k0 + c4 * 4);
            float4 b = *(const float4*)(Y + (size_t)(bn + r) * D + k0 + c4 * 4);
            As[c4 * 4 + 0][r] = a.x; As[c4 * 4 + 1][r] = a.y;
            As[c4 * 4 + 2][r] = a.z; As[c4 * 4 + 3][r] = a.w;
            Bs[c4 * 4 + 0][r] = b.x; Bs[c4 * 4 + 1][r] = b.y;
            Bs[c4 * 4 + 2][r] = b.z; Bs[c4 * 4 + 3][r] = b.w;
        }
        __syncthreads();
#pragma unroll
        for (int kk = 0; kk < 16; ++kk) {
            float a[8], b[8];
            *(float4*)(a)     = *(const float4*)&As[kk][ty * 8];
            *(float4*)(a + 4) = *(const float4*)&As[kk][ty * 8 + 4];
            *(float4*)(b)     = *(const float4*)&Bs[kk][tx * 8];
            *(float4*)(b + 4) = *(const float4*)&Bs[kk][tx * 8 + 4];
#pragma unroll
            for (int i = 0; i < 8; ++i)
#pragma unroll
                for (int j = 0; j < 8; ++j) acc[i][j] += a[i] * b[j];
        }
        __syncthreads();
    }

#pragma unroll
    for (int i = 0; i < 8; ++i) {
        int row = bm + ty * 8 + i;
        __nv_bfloat162 pk[4];
#pragma unroll
        for (int k = 0; k < 4; ++k)
            pk[k] = __floats2bfloat162_rn(2.f * acc[i][2 * k], 2.f * acc[i][2 * k + 1]);
        *(uint4*)(d_S + (size_t)row * (N / 2) + (bn + tx * 8) / 2) = *(uint4*)pk;
    }
#pragma unroll
    for (int j = 0; j < 8; ++j) {
        int trow = bn + tx * 8 + j;
        __nv_bfloat162 pk[4];
#pragma unroll
        for (int k = 0; k < 4; ++k)
            pk[k] = __floats2bfloat162_rn(2.f * acc[2 * k][j], 2.f * acc[2 * k + 1][j]);
        *(uint4*)(d_St + (size_t)trow * (N / 2) + (bm + ty * 8) / 2) = *(uint4*)pk;
    }
}

__device__ __forceinline__ void unpack8(uint4 u, float* v) {
    v[0] = __uint_as_float(u.x << 16);
    v[1] = __uint_as_float(u.x & 0xFFFF0000u);
    v[2] = __uint_as_float(u.y << 16);
    v[3] = __uint_as_float(u.y & 0xFFFF0000u);
    v[4] = __uint_as_float(u.z << 16);
    v[5] = __uint_as_float(u.z & 0xFFFF0000u);
    v[6] = __uint_as_float(u.w << 16);
    v[7] = __uint_as_float(u.w & 0xFFFF0000u);
}

/* ======= EXACT 2-pass: out_h[row] = logw - LSE_j(vec_h[j] + S[row][j]);
   also stores the exact row max into mrow[] to seed the fast kernel ======= */
__global__ void __launch_bounds__(256) lse_kernel(const uint4* __restrict__ S,
                                                  const float* __restrict__ vh,
                                                  float* __restrict__ outh,
                                                  float* __restrict__ mrow,
                                                  float logw) {
    __shared__ float gs[N];
    __shared__ float redM[8];
    __shared__ float redS[8];
    int tid = threadIdx.x;
#pragma unroll
    for (int c = 0; c < 4; ++c)
        ((float4*)gs)[tid + c * 256] = ((const float4*)vh)[tid + c * 256];
    __syncthreads();
    int warp = tid >> 5, lane = tid & 31;

    for (int r = 0; r < RPB; ++r) {
        int row = blockIdx.x * RPB + r;
        const uint4* Sr = S + (size_t)row * (N / 8);
        float v[16];
        float lm = -1e30f;
#pragma unroll
        for (int c = 0; c < 2; ++c) {
            int idx = tid + c * 256;
            uint4 u = Sr[idx];
            float sv[8];
            unpack8(u, sv);
            float4 gA = ((const float4*)gs)[2 * idx];
            float4 gB = ((const float4*)gs)[2 * idx + 1];
            float* vv = v + c * 8;
            vv[0] = gA.x + sv[0]; vv[1] = gA.y + sv[1];
            vv[2] = gA.z + sv[2]; vv[3] = gA.w + sv[3];
            vv[4] = gB.x + sv[4]; vv[5] = gB.y + sv[5];
            vv[6] = gB.z + sv[6]; vv[7] = gB.w + sv[7];
#pragma unroll
            for (int k = 0; k < 8; k += 4)
                lm = fmaxf(lm, fmaxf(fmaxf(vv[k], vv[k + 1]),
                                     fmaxf(vv[k + 2], vv[k + 3])));
        }
#pragma unroll
        for (int o = 16; o; o >>= 1) lm = fmaxf(lm, __shfl_xor_sync(0xffffffffu, lm, o));
        if (lane == 0) redM[warp] = lm;
        __syncthreads();
        float m = redM[0];
#pragma unroll
        for (int k = 1; k < 8; ++k) m = fmaxf(m, redM[k]);

        float ls = 0.f;
#pragma unroll
        for (int k = 0; k < 16; ++k) {
            float dd = v[k] - m;
            if (dd > THRESH) ls += __expf(dd);
        }
#pragma unroll
        for (int o = 16; o; o >>= 1) ls += __shfl_xor_sync(0xffffffffu, ls, o);
        if (lane == 0) redS[warp] = ls;
        __syncthreads();
        if (tid == 0) {
            float s = redS[0];
#pragma unroll
            for (int k = 1; k < 8; ++k) s += redS[k];
            outh[row] = logw - (m + __logf(s));
            mrow[row] = m;
        }
        __syncthreads();
    }
}

/* ======= FAST 1-pass screened LSE: one warp per row, carried shift =======
   shift = mrow[row] (>= approx row max). bf16 SIMD screen selects the rare
   chunks near the max; exact fp32 sum on those. New approx max is tracked
   over ALL chunks and stored (+margin) for the next iteration.            */
__global__ void __launch_bounds__(256) lse_fast_kernel(const uint4* __restrict__ S,
                                                       const float* __restrict__ vh,
                                                       float* __restrict__ outh,
                                                       float* __restrict__ mrow,
                                                       float logw) {
    __shared__ float gsf[N];               /* gh fp32, 16 KB */
    __shared__ __nv_bfloat162 gs2[N / 2];  /* gh bf16x2, 8 KB */
    int tid = threadIdx.x;
#pragma unroll
    for (int c = 0; c < 4; ++c) {
        float4 v = ((const float4*)vh)[tid + c * 256];
        ((float4*)gsf)[tid + c * 256] = v;
        gs2[(tid + c * 256) * 2]     = __floats2bfloat162_rn(v.x, v.y);
        gs2[(tid + c * 256) * 2 + 1] = __floats2bfloat162_rn(v.z, v.w);
    }
    __syncthreads();
    int warp = tid >> 5, lane = tid & 31;
    int row = blockIdx.x * 8 + warp;
    float shift = mrow[row];
    float hthr = shift - 36.0f;
    const uint4* Sr = S + (size_t)row * (N / 8);
    const uint4* G2 = (const uint4*)gs2;   /* 4 bf16x2 per uint4 = 8 elems */
    const float4* GF = (const float4*)gsf;
    __nv_bfloat162 wm2 = __floats2bfloat162_rn(-3.0e4f, -3.0e4f);
    float ls = 0.f;

#pragma unroll 4
    for (int c = 0; c < 16; ++c) {
        int idx = lane + 32 * c;
        uint4 u = Sr[idx];
        uint4 g = G2[idx];
        __nv_bfloat162 h0 = __hadd2(*(__nv_bfloat162*)&u.x, *(__nv_bfloat162*)&g.x);
        __nv_bfloat162 h1 = __hadd2(*(__nv_bfloat162*)&u.y, *(__nv_bfloat162*)&g.y);
        __nv_bfloat162 h2 = __hadd2(*(__nv_bfloat162*)&u.z, *(__nv_bfloat162*)&g.z);
        __nv_bfloat162 h3 = __hadd2(*(__nv_bfloat162*)&u.w, *(__nv_bfloat162*)&g.w);
        __nv_bfloat162 mm = __hmax2(__hmax2(h0, h1), __hmax2(h2, h3));
        wm2 = __hmax2(wm2, mm);
        float cm = fmaxf(__low2float(mm), __high2float(mm));
        if (cm > hthr) {
            float sv[8];
            unpack8(u, sv);
            float4 gA = GF[2 * idx];
            float4 gB = GF[2 * idx + 1];
            float t0 = gA.x + sv[0] - shift;
            float t1 = gA.y + sv[1] - shift;
            float t2 = gA.z + sv[2] - shift;
            float t3 = gA.w + sv[3] - shift;
            float t4 = gB.x + sv[4] - shift;
            float t5 = gB.y + sv[5] - shift;
            float t6 = gB.z + sv[6] - shift;
            float t7 = gB.w + sv[7] - shift;
            ls += __expf(fminf(t0, 60.f)) + __expf(fminf(t1, 60.f));
            ls += __expf(fminf(t2, 60.f)) + __expf(fminf(t3, 60.f));
            ls += __expf(fminf(t4, 60.f)) + __expf(fminf(t5, 60.f));
            ls += __expf(fminf(t6, 60.f)) + __expf(fminf(t7, 60.f));
        }
    }
#pragma unroll
    for (int o = 16; o; o >>= 1) {
        unsigned ow = __shfl_xor_sync(0xffffffffu, *(unsigned*)&wm2, o);
        wm2 = __hmax2(wm2, *(__nv_bfloat162*)&ow);
        ls += __shfl_xor_sync(0xffffffffu, ls, o);
    }
    if (lane == 0) {
        float wm = fmaxf(__low2float(wm2), __high2float(wm2));
        ls = fmaxf(ls, 1e-37f);
        outh[row] = logw - (shift + __logf(ls));
        mrow[row] = wm + 3.0f;     /* shift for the next iteration */
    }
}

/* ======= out[row] = sum_j exp(scal_h[row] + vec_h[j] + S[row][j]) ======= */
__global__ void __launch_bounds__(256) psum_kernel(const uint4* __restrict__ S,
                                                   const float* __restrict__ vh,
                                                   const float* __restrict__ scalh,
                                                   float* __restrict__ outv) {
    __shared__ float gs[N];
    __shared__ float redS[8];
    int tid = threadIdx.x;
#pragma unroll
    for (int c = 0; c < 4; ++c)
        ((float4*)gs)[tid + c * 256] = ((const float4*)vh)[tid + c * 256];
    __syncthreads();
    int warp = tid >> 5, lane = tid & 31;

    for (int r = 0; r < RPB; ++r) {
        int row = blockIdx.x * RPB + r;
        float fr = scalh[row];
        const uint4* Sr = S + (size_t)row * (N / 8);
        float ls = 0.f;
#pragma unroll
        for (int c = 0; c < 2; ++c) {
            int idx = tid + c * 256;
            uint4 u = Sr[idx];
            float sv[8];
            unpack8(u, sv);
            float4 gA = ((const float4*)gs)[2 * idx];
            float4 gB = ((const float4*)gs)[2 * idx + 1];
            float t[8];
            t[0] = fr + gA.x + sv[0]; t[1] = fr + gA.y + sv[1];
            t[2] = fr + gA.z + sv[2]; t[3] = fr + gA.w + sv[3];
            t[4] = fr + gB.x + sv[4]; t[5] = fr + gB.y + sv[5];
            t[6] = fr + gB.z + sv[6]; t[7] = fr + gB.w + sv[7];
#pragma unroll
            for (int k = 0; k < 8; ++k)
                if (t[k] > THRESH_P) ls += __expf(t[k]);
        }
#pragma unroll
        for (int o = 16; o; o >>= 1) ls += __shfl_xor_sync(0xffffffffu, ls, o);
        if (lane == 0) redS[warp] = ls;
        __syncthreads();
        if (tid == 0) {
            float s = redS[0];
#pragma unroll
            for (int k = 1; k < 8; ++k) s += redS[k];
            outv[row] = s;
        }
        __syncthreads();
    }
}

/* loss = sum_i f_i R_i + sum_j g_j C_j - (la+lb+1) * sum R + 1
   with f = fh + x2, g = gh + y2                                          */
__global__ void __launch_bounds__(256) final_kernel(float* __restrict__ out) {
    int tid = threadIdx.x;
    double acc = 0.0;
    const double k = (double)LA + (double)LB + 1.0;
    for (int i = tid; i < N; i += 256) {
        double Ri = (double)d_R[i];
        double fi = (double)d_fh[i] + (double)d_x2[i];
        double gi = (double)d_gh[i] + (double)d_y2[i];
        acc += fi * Ri + gi * (double)d_C[i] - k * Ri;
    }
    __shared__ double red[256];
    red[tid] = acc;
    __syncthreads();
    for (int o = 128; o; o >>= 1) {
        if (tid < o) red[tid] += red[tid + o];
        __syncthreads();
    }
    if (tid == 0) out[0] = (float)(red[0] + 1.0);
}

/* ================================================================= */
extern "C" void kernel_launch(void* const* d_in, const int* in_sizes, int n_in,
                              void* d_out, int out_size) {
    (void)in_sizes; (void)n_in; (void)out_size;
    const float* x = (const float*)d_in[0];
    const float* y = (const float*)d_in[1];
    float* out = (float*)d_out;

    void *pS_, *pSt_, *pfh_, *pgh_, *pmf_, *pmg_, *pR_, *pC_;
    cudaGetSymbolAddress(&pS_,  d_S);
    cudaGetSymbolAddress(&pSt_, d_St);
    cudaGetSymbolAddress(&pfh_, d_fh);
    cudaGetSymbolAddress(&pgh_, d_gh);
    cudaGetSymbolAddress(&pmf_, d_mf);
    cudaGetSymbolAddress(&pmg_, d_mg);
    cudaGetSymbolAddress(&pR_,  d_R);
    cudaGetSymbolAddress(&pC_,  d_C);
    const uint4* pS  = (const uint4*)pS_;
    const uint4* pSt = (const uint4*)pSt_;
    float* pfh = (float*)pfh_;
    float* pgh = (float*)pgh_;
    float* pmf = (float*)pmf_;
    float* pmg = (float*)pmg_;
    float* pR  = (float*)pR_;
    float* pC  = (float*)pC_;

    prep_kernel<<<1024, 256>>>(x, y);
    gemm_kernel<<<dim3(32, 32), 256>>>(x, y);

    for (int it = 0; it < N_EXACT; ++it) {
        lse_kernel<<<N / RPB, 256>>>(pS,  pgh, pfh, pmf, LA);
        lse_kernel<<<N / RPB, 256>>>(pSt, pfh, pgh, pmg, LB);
    }
    for (int it = N_EXACT; it < 100; ++it) {
        lse_fast_kernel<<<N / 8, 256>>>(pS,  pgh, pfh, pmf, LA);
        lse_fast_kernel<<<N / 8, 256>>>(pSt, pfh, pgh, pmg, LB);
    }

    psum_kernel<<<N / RPB, 256>>>(pS,  pgh, pfh, pR);
    psum_kernel<<<N / RPB, 256>>>(pSt, pfh, pgh, pC);
    final_kernel<<<1, 256>>>(out);
}

// round 11
// speedup vs baseline: 3.4663x; 1.5724x over previous
#include <cuda_runtime.h>
#include <cuda_bf16.h>

#define N 4096
#define D 512
#define LA (-8.317766166719344f)      /* -ln(4096) */
#define LB (-8.317766166719344f)
#define THRESH (-25.0f)
#define THRESH_P (-40.0f)
#define RPB 4                          /* rows per block in exact LSE/psum */
#define CAP 320                        /* candidate slots per row */

/* ---- scratch (device globals: allocation-free rule) ---- */
__device__ __nv_bfloat162 d_S [(size_t)N * N / 2];   /* 2XY^T bf16, 33.5MB */
__device__ __nv_bfloat162 d_St[(size_t)N * N / 2];   /* transpose          */
__device__ float d_fh[N];              /* f - x2 */
__device__ float d_gh[N];              /* g - y2 */
__device__ float d_x2[N];
__device__ float d_y2[N];
__device__ float d_mf[N];              /* carried row-max shift, f pass */
__device__ float d_mg[N];              /* carried row-max shift, g pass */
__device__ float d_R[N];
__device__ float d_C[N];
__device__ unsigned short d_idxf[(size_t)N * CAP];   /* candidate lists */
__device__ unsigned short d_idxg[(size_t)N * CAP];
__device__ int d_cntf[N];
__device__ int d_cntg[N];

/* ================= prep ================= */
__global__ void __launch_bounds__(256) prep_kernel(const float* __restrict__ x,
                                                   const float* __restrict__ y) {
    int warp = threadIdx.x >> 5, lane = threadIdx.x & 31;
    int id = blockIdx.x * 8 + warp;
    const float* src = (id < N) ? x : y;
    int row = (id < N) ? id : id - N;
    const float4* p = (const float4*)(src + (size_t)row * D);
    float s = 0.f;
#pragma unroll
    for (int k = 0; k < 4; ++k) {
        float4 v = p[lane + 32 * k];
        s += v.x * v.x + v.y * v.y + v.z * v.z + v.w * v.w;
    }
#pragma unroll
    for (int o = 16; o; o >>= 1) s += __shfl_xor_sync(0xffffffffu, s, o);
    if (lane == 0) {
        if (id < N) { d_x2[row] = s; d_fh[row] = -s; }
        else        { d_y2[row] = s; d_gh[row] = -s; }
    }
}

/* ============ S = 2 X Y^T (bf16), also writes S^T ============ */
__global__ void __launch_bounds__(256) gemm_kernel(const float* __restrict__ X,
                                                   const float* __restrict__ Y) {
    __shared__ float As[16][132];
    __shared__ float Bs[16][132];
    int tid = threadIdx.x;
    int tx = tid & 15, ty = tid >> 4;
    int bm = blockIdx.y * 128, bn = blockIdx.x * 128;
    float acc[8][8];
#pragma unroll
    for (int i = 0; i < 8; ++i)
#pragma unroll
        for (int j = 0; j < 8; ++j) acc[i][j] = 0.f;

    for (int k0 = 0; k0 < D; k0 += 16) {
#pragma unroll
        for (int l = 0; l < 2; ++l) {
            int t2 = tid + l * 256;
            int r = t2 >> 2, c4 = t2 & 3;
            float4 a = *(const float4*)(X + (size_t)(bm + r) * D + k0 + c4 * 4);
            float4 b = *(const float4*)(Y + (size_t)(bn + r) * D + k0 + c4 * 4);
            As[c4 * 4 + 0][r] = a.x; As[c4 * 4 + 1][r] = a.y;
            As[c4 * 4 + 2][r] = a.z; As[c4 * 4 + 3][r] = a.w;
            Bs[c4 * 4 + 0][r] = b.x; Bs[c4 * 4 + 1][r] = b.y;
            Bs[c4 * 4 + 2][r] = b.z; Bs[c4 * 4 + 3][r] = b.w;
        }
        __syncthreads();
#pragma unroll
        for (int kk = 0; kk < 16; ++kk) {
            float a[8], b[8];
            *(float4*)(a)     = *(const float4*)&As[kk][ty * 8];
            *(float4*)(a + 4) = *(const float4*)&As[kk][ty * 8 + 4];
            *(float4*)(b)     = *(const float4*)&Bs[kk][tx * 8];
            *(float4*)(b + 4) = *(const float4*)&Bs[kk][tx * 8 + 4];
#pragma unroll
            for (int i = 0; i < 8; ++i)
#pragma unroll
                for (int j = 0; j < 8; ++j) acc[i][j] += a[i] * b[j];
        }
        __syncthreads();
    }

#pragma unroll
    for (int i = 0; i < 8; ++i) {
        int row = bm + ty * 8 + i;
        __nv_bfloat162 pk[4];
#pragma unroll
        for (int k = 0; k < 4; ++k)
            pk[k] = __floats2bfloat162_rn(2.f * acc[i][2 * k], 2.f * acc[i][2 * k + 1]);
        *(uint4*)(d_S + (size_t)row * (N / 2) + (bn + tx * 8) / 2) = *(uint4*)pk;
    }
#pragma unroll
    for (int j = 0; j < 8; ++j) {
        int trow = bn + tx * 8 + j;
        __nv_bfloat162 pk[4];
#pragma unroll
        for (int k = 0; k < 4; ++k)
            pk[k] = __floats2bfloat162_rn(2.f * acc[2 * k][j], 2.f * acc[2 * k + 1][j]);
        *(uint4*)(d_St + (size_t)trow * (N / 2) + (bm + ty * 8) / 2) = *(uint4*)pk;
    }
}

__device__ __forceinline__ void unpack8(uint4 u, float* v) {
    v[0] = __uint_as_float(u.x << 16);
    v[1] = __uint_as_float(u.x & 0xFFFF0000u);
    v[2] = __uint_as_float(u.y << 16);
    v[3] = __uint_as_float(u.y & 0xFFFF0000u);
    v[4] = __uint_as_float(u.z << 16);
    v[5] = __uint_as_float(u.z & 0xFFFF0000u);
    v[6] = __uint_as_float(u.w << 16);
    v[7] = __uint_as_float(u.w & 0xFFFF0000u);
}

/* ======= EXACT 2-pass LSE (seed iterations); also stores exact row max ======= */
__global__ void __launch_bounds__(256) lse_kernel(const uint4* __restrict__ S,
                                                  const float* __restrict__ vh,
                                                  float* __restrict__ outh,
                                                  float* __restrict__ mrow,
                                                  float logw) {
    __shared__ float gs[N];
    __shared__ float redM[8];
    __shared__ float redS[8];
    int tid = threadIdx.x;
#pragma unroll
    for (int c = 0; c < 4; ++c)
        ((float4*)gs)[tid + c * 256] = ((const float4*)vh)[tid + c * 256];
    __syncthreads();
    int warp = tid >> 5, lane = tid & 31;

    for (int r = 0; r < RPB; ++r) {
        int row = blockIdx.x * RPB + r;
        const uint4* Sr = S + (size_t)row * (N / 8);
        float v[16];
        float lm = -1e30f;
#pragma unroll
        for (int c = 0; c < 2; ++c) {
            int idx = tid + c * 256;
            uint4 u = Sr[idx];
            float sv[8];
            unpack8(u, sv);
            float4 gA = ((const float4*)gs)[2 * idx];
            float4 gB = ((const float4*)gs)[2 * idx + 1];
            float* vv = v + c * 8;
            vv[0] = gA.x + sv[0]; vv[1] = gA.y + sv[1];
            vv[2] = gA.z + sv[2]; vv[3] = gA.w + sv[3];
            vv[4] = gB.x + sv[4]; vv[5] = gB.y + sv[5];
            vv[6] = gB.z + sv[6]; vv[7] = gB.w + sv[7];
#pragma unroll
            for (int k = 0; k < 8; k += 4)
                lm = fmaxf(lm, fmaxf(fmaxf(vv[k], vv[k + 1]),
                                     fmaxf(vv[k + 2], vv[k + 3])));
        }
#pragma unroll
        for (int o = 16; o; o >>= 1) lm = fmaxf(lm, __shfl_xor_sync(0xffffffffu, lm, o));
        if (lane == 0) redM[warp] = lm;
        __syncthreads();
        float m = redM[0];
#pragma unroll
        for (int k = 1; k < 8; ++k) m = fmaxf(m, redM[k]);

        float ls = 0.f;
#pragma unroll
        for (int k = 0; k < 16; ++k) {
            float dd = v[k] - m;
            if (dd > THRESH) ls += __expf(dd);
        }
#pragma unroll
        for (int o = 16; o; o >>= 1) ls += __shfl_xor_sync(0xffffffffu, ls, o);
        if (lane == 0) redS[warp] = ls;
        __syncthreads();
        if (tid == 0) {
            float s = redS[0];
#pragma unroll
            for (int k = 1; k < 8; ++k) s += redS[k];
            outh[row] = logw - (m + __logf(s));
            mrow[row] = m;
        }
        __syncthreads();
    }
}

/* ======= REBUILD: screened full scan + candidate-list emission =======
   one warp per row. Screen chunks at shift-48 (bf16), sum exp over passing
   chunks, emit indices with v > shift-45 into idx[row]. Exact fp32 max over
   passing chunks (contains the row argmax) refreshes the shift.          */
__global__ void __launch_bounds__(256) lse_rebuild_kernel(const uint4* __restrict__ S,
                                                          const float* __restrict__ vh,
                                                          float* __restrict__ outh,
                                                          float* __restrict__ mrow,
                                                          unsigned short* __restrict__ idxl,
                                                          int* __restrict__ cntl,
                                                          float logw) {
    __shared__ float gsf[N];               /* gh fp32 */
    __shared__ __nv_bfloat162 gs2[N / 2];  /* gh bf16x2 */
    __shared__ int scnt[8];
    int tid = threadIdx.x;
#pragma unroll
    for (int c = 0; c < 4; ++c) {
        float4 v = ((const float4*)vh)[tid + c * 256];
        ((float4*)gsf)[tid + c * 256] = v;
        gs2[(tid + c * 256) * 2]     = __floats2bfloat162_rn(v.x, v.y);
        gs2[(tid + c * 256) * 2 + 1] = __floats2bfloat162_rn(v.z, v.w);
    }
    if (tid < 8) scnt[tid] = 0;
    __syncthreads();
    int warp = tid >> 5, lane = tid & 31;
    int row = blockIdx.x * 8 + warp;
    float shift = mrow[row];
    float hscreen = shift - 48.0f;
    float hemit   = shift - 45.0f;
    const uint4* Sr = S + (size_t)row * (N / 8);
    const uint4* G2 = (const uint4*)gs2;
    const float4* GF = (const float4*)gsf;
    unsigned short* Ir = idxl + (size_t)row * CAP;
    float ls = 0.f, wm = -1e30f;

#pragma unroll 4
    for (int c = 0; c < 16; ++c) {
        int idx = lane + 32 * c;
        uint4 u = Sr[idx];
        uint4 g = G2[idx];
        __nv_bfloat162 h0 = __hadd2(*(__nv_bfloat162*)&u.x, *(__nv_bfloat162*)&g.x);
        __nv_bfloat162 h1 = __hadd2(*(__nv_bfloat162*)&u.y, *(__nv_bfloat162*)&g.y);
        __nv_bfloat162 h2 = __hadd2(*(__nv_bfloat162*)&u.z, *(__nv_bfloat162*)&g.z);
        __nv_bfloat162 h3 = __hadd2(*(__nv_bfloat162*)&u.w, *(__nv_bfloat162*)&g.w);
        __nv_bfloat162 mm = __hmax2(__hmax2(h0, h1), __hmax2(h2, h3));
        float cm = fmaxf(__low2float(mm), __high2float(mm));
        if (cm > hscreen) {
            float sv[8], t[8];
            unpack8(u, sv);
            float4 gA = GF[2 * idx];
            float4 gB = GF[2 * idx + 1];
            t[0] = gA.x + sv[0]; t[1] = gA.y + sv[1];
            t[2] = gA.z + sv[2]; t[3] = gA.w + sv[3];
            t[4] = gB.x + sv[4]; t[5] = gB.y + sv[5];
            t[6] = gB.z + sv[6]; t[7] = gB.w + sv[7];
            unsigned m8 = 0;
#pragma unroll
            for (int k = 0; k < 8; ++k) {
                wm = fmaxf(wm, t[k]);
                ls += __expf(fminf(t[k] - shift, 60.f));
                m8 |= (t[k] > hemit) ? (1u << k) : 0u;
            }
            if (m8) {
                int ne = __popc(m8);
                int pos = atomicAdd(&scnt[warp], ne);
#pragma unroll
                for (int k = 0; k < 8; ++k) {
                    if ((m8 >> k) & 1u) {
                        if (pos < CAP) Ir[pos] = (unsigned short)(idx * 8 + k);
                        pos++;
                    }
                }
            }
        }
    }
#pragma unroll
    for (int o = 16; o; o >>= 1) {
        wm = fmaxf(wm, __shfl_xor_sync(0xffffffffu, wm, o));
        ls += __shfl_xor_sync(0xffffffffu, ls, o);
    }
    __syncwarp();
    if (lane == 0) {
        int c = scnt[warp]; if (c > CAP) c = CAP;
        cntl[row] = c;
        ls = fmaxf(ls, 1e-37f);
        outh[row] = logw - (shift + __logf(ls));
        mrow[row] = wm + 1.0f;
    }
}

/* ======= SPARSE pass: sum over candidate list only (one warp/row) ======= */
__global__ void __launch_bounds__(256) lse_sparse_kernel(const __nv_bfloat16* __restrict__ S,
                                                         const float* __restrict__ vh,
                                                         float* __restrict__ outh,
                                                         float* __restrict__ mrow,
                                                         const unsigned short* __restrict__ idxl,
                                                         const int* __restrict__ cntl,
                                                         float logw) {
    int tid = threadIdx.x;
    int warp = tid >> 5, lane = tid & 31;
    int row = blockIdx.x * 8 + warp;
    float shift = mrow[row];
    int cnt = cntl[row];
    const unsigned short* Ir = idxl + (size_t)row * CAP;
    const __nv_bfloat16* Sr = S + (size_t)row * N;
    float ls = 0.f, wm = -1e30f;
    for (int e = lane; e < cnt; e += 32) {
        int j = Ir[e];
        float v = vh[j] + __bfloat162float(Sr[j]);
        wm = fmaxf(wm, v);
        ls += __expf(fminf(v - shift, 60.f));
    }
#pragma unroll
    for (int o = 16; o; o >>= 1) {
        wm = fmaxf(wm, __shfl_xor_sync(0xffffffffu, wm, o));
        ls += __shfl_xor_sync(0xffffffffu, ls, o);
    }
    if (lane == 0) {
        ls = fmaxf(ls, 1e-37f);
        outh[row] = logw - (shift + __logf(ls));
        mrow[row] = wm + 1.0f;
    }
}

/* ======= exact P row/col sums (final, 2 launches) ======= */
__global__ void __launch_bounds__(256) psum_kernel(const uint4* __restrict__ S,
                                                   const float* __restrict__ vh,
                                                   const float* __restrict__ scalh,
                                                   float* __restrict__ outv) {
    __shared__ float gs[N];
    __shared__ float redS[8];
    int tid = threadIdx.x;
#pragma unroll
    for (int c = 0; c < 4; ++c)
        ((float4*)gs)[tid + c * 256] = ((const float4*)vh)[tid + c * 256];
    __syncthreads();
    int warp = tid >> 5, lane = tid & 31;

    for (int r = 0; r < RPB; ++r) {
        int row = blockIdx.x * RPB + r;
        float fr = scalh[row];
        const uint4* Sr = S + (size_t)row * (N / 8);
        float ls = 0.f;
#pragma unroll
        for (int c = 0; c < 2; ++c) {
            int idx = tid + c * 256;
            uint4 u = Sr[idx];
            float sv[8];
            unpack8(u, sv);
            float4 gA = ((const float4*)gs)[2 * idx];
            float4 gB = ((const float4*)gs)[2 * idx + 1];
            float t[8];
            t[0] = fr + gA.x + sv[0]; t[1] = fr + gA.y + sv[1];
            t[2] = fr + gA.z + sv[2]; t[3] = fr + gA.w + sv[3];
            t[4] = fr + gB.x + sv[4]; t[5] = fr + gB.y + sv[5];
            t[6] = fr + gB.z + sv[6]; t[7] = fr + gB.w + sv[7];
#pragma unroll
            for (int k = 0; k < 8; ++k)
                if (t[k] > THRESH_P) ls += __expf(t[k]);
        }
#pragma unroll
        for (int o = 16; o; o >>= 1) ls += __shfl_xor_sync(0xffffffffu, ls, o);
        if (lane == 0) redS[warp] = ls;
        __syncthreads();
        if (tid == 0) {
            float s = redS[0];
#pragma unroll
            for (int k = 1; k < 8; ++k) s += redS[k];
            outv[row] = s;
        }
        __syncthreads();
    }
}

/* loss = sum_i f_i R_i + sum_j g_j C_j - (la+lb+1) * sum R + 1 */
__global__ void __launch_bounds__(256) final_kernel(float* __restrict__ out) {
    int tid = threadIdx.x;
    double acc = 0.0;
    const double k = (double)LA + (double)LB + 1.0;
    for (int i = tid; i < N; i += 256) {
        double Ri = (double)d_R[i];
        double fi = (double)d_fh[i] + (double)d_x2[i];
        double gi = (double)d_gh[i] + (double)d_y2[i];
        acc += fi * Ri + gi * (double)d_C[i] - k * Ri;
    }
    __shared__ double red[256];
    red[tid] = acc;
    __syncthreads();
    for (int o = 128; o; o >>= 1) {
        if (tid < o) red[tid] += red[tid + o];
        __syncthreads();
    }
    if (tid == 0) out[0] = (float)(red[0] + 1.0);
}

/* ================================================================= */
extern "C" void kernel_launch(void* const* d_in, const int* in_sizes, int n_in,
                              void* d_out, int out_size) {
    (void)in_sizes; (void)n_in; (void)out_size;
    const float* x = (const float*)d_in[0];
    const float* y = (const float*)d_in[1];
    float* out = (float*)d_out;

    void *pS_, *pSt_, *pfh_, *pgh_, *pmf_, *pmg_, *pR_, *pC_;
    void *pif_, *pig_, *pcf_, *pcg_;
    cudaGetSymbolAddress(&pS_,  d_S);
    cudaGetSymbolAddress(&pSt_, d_St);
    cudaGetSymbolAddress(&pfh_, d_fh);
    cudaGetSymbolAddress(&pgh_, d_gh);
    cudaGetSymbolAddress(&pmf_, d_mf);
    cudaGetSymbolAddress(&pmg_, d_mg);
    cudaGetSymbolAddress(&pR_,  d_R);
    cudaGetSymbolAddress(&pC_,  d_C);
    cudaGetSymbolAddress(&pif_, d_idxf);
    cudaGetSymbolAddress(&pig_, d_idxg);
    cudaGetSymbolAddress(&pcf_, d_cntf);
    cudaGetSymbolAddress(&pcg_, d_cntg);
    const uint4* pS  = (const uint4*)pS_;
    const uint4* pSt = (const uint4*)pSt_;
    float* pfh = (float*)pfh_;
    float* pgh = (float*)pgh_;
    float* pmf = (float*)pmf_;
    float* pmg = (float*)pmg_;
    float* pR  = (float*)pR_;
    float* pC  = (float*)pC_;
    unsigned short* pif = (unsigned short*)pif_;
    unsigned short* pig = (unsigned short*)pig_;
    int* pcf = (int*)pcf_;
    int* pcg = (int*)pcg_;

    prep_kernel<<<1024, 256>>>(x, y);
    gemm_kernel<<<dim3(32, 32), 256>>>(x, y);

    for (int it = 0; it < 4; ++it) {
        lse_kernel<<<N / RPB, 256>>>(pS,  pgh, pfh, pmf, LA);
        lse_kernel<<<N / RPB, 256>>>(pSt, pfh, pgh, pmg, LB);
    }
    for (int it = 4; it < 100; ++it) {
        bool rb = (it == 4) || (it == 8) || (it >= 16 && ((it - 16) % 16 == 0));
        if (rb) {
            lse_rebuild_kernel<<<N / 8, 256>>>(pS,  pgh, pfh, pmf, pif, pcf, LA);
            lse_rebuild_kernel<<<N / 8, 256>>>(pSt, pfh, pgh, pmg, pig, pcg, LB);
        } else {
            lse_sparse_kernel<<<N / 8, 256>>>((const __nv_bfloat16*)pS,  pgh, pfh, pmf, pif, pcf, LA);
            lse_sparse_kernel<<<N / 8, 256>>>((const __nv_bfloat16*)pSt, pfh, pgh, pmg, pig, pcg, LB);
        }
    }

    psum_kernel<<<N / RPB, 256>>>(pS,  pgh, pfh, pR);
    psum_kernel<<<N / RPB, 256>>>(pSt, pfh, pgh, pC);
    final_kernel<<<1, 256>>>(out);
}

// round 13
// speedup vs baseline: 3.6596x; 1.0558x over previous
#include <cuda_runtime.h>
#include <cuda_bf16.h>
#include <cstdint>

#define N 4096
#define D 512
#define LA (-8.317766166719344f)      /* -ln(4096) */
#define LB (-8.317766166719344f)
#define THRESH (-25.0f)
#define THRESH_P (-40.0f)
#define RPB 4
#define CAP 320
#define PBLK 256                       /* persistent blocks (<=2/SM, co-resident) */

/* ---- scratch (device globals) ---- */
__device__ __nv_bfloat162 d_S [(size_t)N * N / 2];
__device__ __nv_bfloat162 d_St[(size_t)N * N / 2];
__device__ __nv_bfloat16 d_Xb[(size_t)N * D];
__device__ __nv_bfloat16 d_Yb[(size_t)N * D];
__device__ float d_fh[N];
__device__ float d_gh[N];
__device__ float d_x2[N];
__device__ float d_y2[N];
__device__ float d_mf[N];
__device__ float d_mg[N];
__device__ float d_R[N];
__device__ float d_C[N];
__device__ unsigned short d_idxf[(size_t)N * CAP];
__device__ unsigned short d_idxg[(size_t)N * CAP];
__device__ int d_cntf[N];
__device__ int d_cntg[N];
__device__ unsigned d_bar_count;
__device__ volatile unsigned d_bar_gen;

__device__ __forceinline__ uint32_t smem_u32(const void* p) {
    uint32_t a;
    asm("{ .reg .u64 t; cvta.to.shared.u64 t, %1; cvt.u32.u64 %0, t; }"
        : "=r"(a) : "l"(p));
    return a;
}
__device__ __forceinline__ float bf16_raw_to_f(unsigned short s) {
    return __uint_as_float((unsigned)s << 16);
}

/* ================= prep: norms, fh/gh init, bf16 copies, barrier init ===== */
__global__ void __launch_bounds__(256) prep_kernel(const float* __restrict__ x,
                                                   const float* __restrict__ y) {
    if (blockIdx.x == 0 && threadIdx.x == 0) { d_bar_count = 0; d_bar_gen = 0; }
    int warp = threadIdx.x >> 5, lane = threadIdx.x & 31;
    int id = blockIdx.x * 8 + warp;
    const float* src = (id < N) ? x : y;
    __nv_bfloat16* dstb = (id < N) ? d_Xb : d_Yb;
    int row = (id < N) ? id : id - N;
    const float4* p = (const float4*)(src + (size_t)row * D);
    float s = 0.f;
#pragma unroll
    for (int k = 0; k < 4; ++k) {
        float4 v = p[lane + 32 * k];
        s += v.x * v.x + v.y * v.y + v.z * v.z + v.w * v.w;
        __nv_bfloat162 b0 = __floats2bfloat162_rn(v.x, v.y);
        __nv_bfloat162 b1 = __floats2bfloat162_rn(v.z, v.w);
        uint2 u = make_uint2(*(unsigned*)&b0, *(unsigned*)&b1);
        *(uint2*)(dstb + (size_t)row * D + (lane + 32 * k) * 4) = u;
    }
#pragma unroll
    for (int o = 16; o; o >>= 1) s += __shfl_xor_sync(0xffffffffu, s, o);
    if (lane == 0) {
        if (id < N) { d_x2[row] = s; d_fh[row] = -s; }
        else        { d_y2[row] = s; d_gh[row] = -s; }
    }
}

/* ============ tensor-core GEMM: S = 2 X Y^T (bf16), also writes S^T ======== */
#define BK 64
__global__ void __launch_bounds__(256) gemm_tc_kernel() {
    __shared__ __align__(16) char smem_raw[128 * 136 * 2];  /* 34816 B */
    __nv_bfloat16* As = (__nv_bfloat16*)smem_raw;           /* [128][64] swz */
    __nv_bfloat16* Bs = As + 128 * BK;
    __nv_bfloat16* Ct = (__nv_bfloat16*)smem_raw;           /* [128][136]    */

    int tid = threadIdx.x;
    int warp = tid >> 5, lane = tid & 31;
    int wm = warp >> 2, wn = warp & 3;                      /* 2x4 warps     */
    int bm = blockIdx.y * 128, bn = blockIdx.x * 128;

    float acc[4][4][4];
#pragma unroll
    for (int mi = 0; mi < 4; ++mi)
#pragma unroll
        for (int ni = 0; ni < 4; ++ni)
#pragma unroll
            for (int k = 0; k < 4; ++k) acc[mi][ni][k] = 0.f;

    uint32_t baseA = smem_u32(As), baseB = smem_u32(Bs);

    for (int k0 = 0; k0 < D; k0 += BK) {
        /* load tiles: 128 rows x 64 bf16 each; swizzled 16B chunks */
        uint4* Av = (uint4*)As;
        uint4* Bv = (uint4*)Bs;
#pragma unroll
        for (int l = 0; l < 4; ++l) {
            int u = tid + l * 256;                          /* 0..1023 */
            int r = u >> 3, c = u & 7;
            int pc = c ^ (r & 7);
            Av[r * 8 + pc] = *(const uint4*)(d_Xb + (size_t)(bm + r) * D + k0 + c * 8);
            Bv[r * 8 + pc] = *(const uint4*)(d_Yb + (size_t)(bn + r) * D + k0 + c * 8);
        }
        __syncthreads();

#pragma unroll
        for (int ks = 0; ks < BK / 16; ++ks) {
            uint32_t a[4][4], b[2][4];
#pragma unroll
            for (int mi = 0; mi < 4; ++mi) {
                int row = wm * 64 + mi * 16 + (lane & 15);
                int lc = ks * 2 + (lane >> 4);
                uint32_t addr = baseA + (uint32_t)(row * 8 + (lc ^ (row & 7))) * 16;
                asm volatile("ldmatrix.sync.aligned.m8n8.x4.shared.b16 {%0,%1,%2,%3},[%4];"
                             : "=r"(a[mi][0]), "=r"(a[mi][1]), "=r"(a[mi][2]), "=r"(a[mi][3])
                             : "r"(addr));
            }
#pragma unroll
            for (int nj = 0; nj < 2; ++nj) {
                int jrow = wn * 32 + nj * 16 + (lane & 7) + ((lane >> 3) & 1) * 8;
                int lc = ks * 2 + (lane >> 4);
                uint32_t addr = baseB + (uint32_t)(jrow * 8 + (lc ^ (jrow & 7))) * 16;
                asm volatile("ldmatrix.sync.aligned.m8n8.x4.shared.b16 {%0,%1,%2,%3},[%4];"
                             : "=r"(b[nj][0]), "=r"(b[nj][1]), "=r"(b[nj][2]), "=r"(b[nj][3])
                             : "r"(addr));
            }
#pragma unroll
            for (int mi = 0; mi < 4; ++mi)
#pragma unroll
                for (int ni = 0; ni < 4; ++ni) {
                    uint32_t b0 = b[ni >> 1][(ni & 1)];
                    uint32_t b1 = b[ni >> 1][(ni & 1) + 2];
                    asm volatile(
                        "mma.sync.aligned.m16n8k16.row.col.f32.bf16.bf16.f32 "
                        "{%0,%1,%2,%3},{%4,%5,%6,%7},{%8,%9},{%0,%1,%2,%3};"
                        : "+f"(acc[mi][ni][0]), "+f"(acc[mi][ni][1]),
                          "+f"(acc[mi][ni][2]), "+f"(acc[mi][ni][3])
                        : "r"(a[mi][0]), "r"(a[mi][1]), "r"(a[mi][2]), "r"(a[mi][3]),
                          "r"(b0), "r"(b1));
                }
        }
        __syncthreads();
    }

    /* stage 2*C into smem bf16 [128][136] */
    int g = lane >> 2, t4 = lane & 3;
#pragma unroll
    for (int mi = 0; mi < 4; ++mi)
#pragma unroll
        for (int ni = 0; ni < 4; ++ni) {
            int col = wn * 32 + ni * 8 + t4 * 2;
            int r0 = wm * 64 + mi * 16 + g;
            __nv_bfloat162 p0 = __floats2bfloat162_rn(2.f * acc[mi][ni][0], 2.f * acc[mi][ni][1]);
            __nv_bfloat162 p1 = __floats2bfloat162_rn(2.f * acc[mi][ni][2], 2.f * acc[mi][ni][3]);
            *(__nv_bfloat162*)&Ct[r0 * 136 + col]       = p0;
            *(__nv_bfloat162*)&Ct[(r0 + 8) * 136 + col] = p1;
        }
    __syncthreads();

    /* S: contiguous row copy */
#pragma unroll
    for (int l = 0; l < 8; ++l) {
        int u = tid + l * 256;                              /* 0..2047 */
        int r = u >> 4, q = u & 15;
        uint4 v = *(uint4*)&Ct[r * 136 + q * 8];
        *(uint4*)((__nv_bfloat16*)d_S + (size_t)(bm + r) * N + bn + q * 8) = v;
    }
    /* St: transpose; thread handles one col, 64 rows */
    {
        int j = tid & 127, half = tid >> 7;
        int r0 = half * 64;
        __nv_bfloat16 hbuf[8];
#pragma unroll
        for (int seg = 0; seg < 8; ++seg) {
#pragma unroll
            for (int rr = 0; rr < 8; ++rr)
                hbuf[rr] = Ct[(r0 + seg * 8 + rr) * 136 + j];
            *(uint4*)((__nv_bfloat16*)d_St + (size_t)(bn + j) * N + bm + r0 + seg * 8)
                = *(uint4*)hbuf;
        }
    }
}

__device__ __forceinline__ void unpack8(uint4 u, float* v) {
    v[0] = __uint_as_float(u.x << 16);
    v[1] = __uint_as_float(u.x & 0xFFFF0000u);
    v[2] = __uint_as_float(u.y << 16);
    v[3] = __uint_as_float(u.y & 0xFFFF0000u);
    v[4] = __uint_as_float(u.z << 16);
    v[5] = __uint_as_float(u.z & 0xFFFF0000u);
    v[6] = __uint_as_float(u.w << 16);
    v[7] = __uint_as_float(u.w & 0xFFFF0000u);
}

/* ======= EXACT 2-pass LSE (seed iterations); stores exact row max ======= */
__global__ void __launch_bounds__(256) lse_kernel(const uint4* __restrict__ S,
                                                  const float* __restrict__ vh,
                                                  float* __restrict__ outh,
                                                  float* __restrict__ mrow,
                                                  float logw) {
    __shared__ float gs[N];
    __shared__ float redM[8];
    __shared__ float redS[8];
    int tid = threadIdx.x;
#pragma unroll
    for (int c = 0; c < 4; ++c)
        ((float4*)gs)[tid + c * 256] = ((const float4*)vh)[tid + c * 256];
    __syncthreads();
    int warp = tid >> 5, lane = tid & 31;

    for (int r = 0; r < RPB; ++r) {
        int row = blockIdx.x * RPB + r;
        const uint4* Sr = S + (size_t)row * (N / 8);
        float v[16];
        float lm = -1e30f;
#pragma unroll
        for (int c = 0; c < 2; ++c) {
            int idx = tid + c * 256;
            uint4 u = Sr[idx];
            float sv[8];
            unpack8(u, sv);
            float4 gA = ((const float4*)gs)[2 * idx];
            float4 gB = ((const float4*)gs)[2 * idx + 1];
            float* vv = v + c * 8;
            vv[0] = gA.x + sv[0]; vv[1] = gA.y + sv[1];
            vv[2] = gA.z + sv[2]; vv[3] = gA.w + sv[3];
            vv[4] = gB.x + sv[4]; vv[5] = gB.y + sv[5];
            vv[6] = gB.z + sv[6]; vv[7] = gB.w + sv[7];
#pragma unroll
            for (int k = 0; k < 8; k += 4)
                lm = fmaxf(lm, fmaxf(fmaxf(vv[k], vv[k + 1]),
                                     fmaxf(vv[k + 2], vv[k + 3])));
        }
#pragma unroll
        for (int o = 16; o; o >>= 1) lm = fmaxf(lm, __shfl_xor_sync(0xffffffffu, lm, o));
        if (lane == 0) redM[warp] = lm;
        __syncthreads();
        float m = redM[0];
#pragma unroll
        for (int k = 1; k < 8; ++k) m = fmaxf(m, redM[k]);

        float ls = 0.f;
#pragma unroll
        for (int k = 0; k < 16; ++k) {
            float dd = v[k] - m;
            if (dd > THRESH) ls += __expf(dd);
        }
#pragma unroll
        for (int o = 16; o; o >>= 1) ls += __shfl_xor_sync(0xffffffffu, ls, o);
        if (lane == 0) redS[warp] = ls;
        __syncthreads();
        if (tid == 0) {
            float s = redS[0];
#pragma unroll
            for (int k = 1; k < 8; ++k) s += redS[k];
            outh[row] = logw - (m + __logf(s));
            mrow[row] = m;
        }
        __syncthreads();
    }
}

/* ======= REBUILD: screened full scan + candidate-list emission ======= */
__global__ void __launch_bounds__(256) lse_rebuild_kernel(const uint4* __restrict__ S,
                                                          const float* __restrict__ vh,
                                                          float* __restrict__ outh,
                                                          float* __restrict__ mrow,
                                                          unsigned short* __restrict__ idxl,
                                                          int* __restrict__ cntl,
                                                          float logw) {
    __shared__ float gsf[N];
    __shared__ __nv_bfloat162 gs2[N / 2];
    __shared__ int scnt[8];
    int tid = threadIdx.x;
#pragma unroll
    for (int c = 0; c < 4; ++c) {
        float4 v = ((const float4*)vh)[tid + c * 256];
        ((float4*)gsf)[tid + c * 256] = v;
        gs2[(tid + c * 256) * 2]     = __floats2bfloat162_rn(v.x, v.y);
        gs2[(tid + c * 256) * 2 + 1] = __floats2bfloat162_rn(v.z, v.w);
    }
    if (tid < 8) scnt[tid] = 0;
    __syncthreads();
    int warp = tid >> 5, lane = tid & 31;
    int row = blockIdx.x * 8 + warp;
    float shift = mrow[row];
    float hscreen = shift - 48.0f;
    float hemit   = shift - 45.0f;
    const uint4* Sr = S + (size_t)row * (N / 8);
    const uint4* G2 = (const uint4*)gs2;
    const float4* GF = (const float4*)gsf;
    unsigned short* Ir = idxl + (size_t)row * CAP;
    float ls = 0.f, wm = -1e30f;

#pragma unroll 4
    for (int c = 0; c < 16; ++c) {
        int idx = lane + 32 * c;
        uint4 u = Sr[idx];
        uint4 g = G2[idx];
        __nv_bfloat162 h0 = __hadd2(*(__nv_bfloat162*)&u.x, *(__nv_bfloat162*)&g.x);
        __nv_bfloat162 h1 = __hadd2(*(__nv_bfloat162*)&u.y, *(__nv_bfloat162*)&g.y);
        __nv_bfloat162 h2 = __hadd2(*(__nv_bfloat162*)&u.z, *(__nv_bfloat162*)&g.z);
        __nv_bfloat162 h3 = __hadd2(*(__nv_bfloat162*)&u.w, *(__nv_bfloat162*)&g.w);
        __nv_bfloat162 mm = __hmax2(__hmax2(h0, h1), __hmax2(h2, h3));
        float cm = fmaxf(__low2float(mm), __high2float(mm));
        if (cm > hscreen) {
            float sv[8], t[8];
            unpack8(u, sv);
            float4 gA = GF[2 * idx];
            float4 gB = GF[2 * idx + 1];
            t[0] = gA.x + sv[0]; t[1] = gA.y + sv[1];
            t[2] = gA.z + sv[2]; t[3] = gA.w + sv[3];
            t[4] = gB.x + sv[4]; t[5] = gB.y + sv[5];
            t[6] = gB.z + sv[6]; t[7] = gB.w + sv[7];
            unsigned m8 = 0;
#pragma unroll
            for (int k = 0; k < 8; ++k) {
                wm = fmaxf(wm, t[k]);
                ls += __expf(fminf(t[k] - shift, 60.f));
                m8 |= (t[k] > hemit) ? (1u << k) : 0u;
            }
            if (m8) {
                int ne = __popc(m8);
                int pos = atomicAdd(&scnt[warp], ne);
#pragma unroll
                for (int k = 0; k < 8; ++k) {
                    if ((m8 >> k) & 1u) {
                        if (pos < CAP) Ir[pos] = (unsigned short)(idx * 8 + k);
                        pos++;
                    }
                }
            }
        }
    }
#pragma unroll
    for (int o = 16; o; o >>= 1) {
        wm = fmaxf(wm, __shfl_xor_sync(0xffffffffu, wm, o));
        ls += __shfl_xor_sync(0xffffffffu, ls, o);
    }
    __syncwarp();
    if (lane == 0) {
        int c = scnt[warp]; if (c > CAP) c = CAP;
        cntl[row] = c;
        ls = fmaxf(ls, 1e-37f);
        outh[row] = logw - (shift + __logf(ls));
        mrow[row] = wm + 1.0f;
    }
}

/* ======= persistent multi-iteration sparse kernel ======= */
__device__ __forceinline__ void grid_barrier() {
    __syncthreads();
    if (threadIdx.x == 0) {
        __threadfence();
        unsigned gen = d_bar_gen;
        if (atomicAdd(&d_bar_count, 1u) == PBLK - 1u) {
            d_bar_count = 0;
            __threadfence();
            d_bar_gen = gen + 1;
        } else {
            while (d_bar_gen == gen) __nanosleep(100);
        }
    }
    __syncthreads();
}

__device__ __forceinline__ void sparse_row(const __nv_bfloat16* __restrict__ S,
                                           const float* __restrict__ vh,
                                           float* __restrict__ outh,
                                           const unsigned short* __restrict__ idxl,
                                           int cnt, int row, float& shift,
                                           float logw, int lane) {
    const unsigned short* Ir = idxl + (size_t)row * CAP;
    const unsigned short* Sr = (const unsigned short*)S + (size_t)row * N;
    float ls = 0.f, wm = -1e30f;
    for (int e = lane; e < cnt; e += 32) {
        int j = __ldg(&Ir[e]);
        float v = __ldcg(&vh[j]) + bf16_raw_to_f(__ldg(&Sr[j]));
        wm = fmaxf(wm, v);
        ls += __expf(fminf(v - shift, 60.f));
    }
#pragma unroll
    for (int o = 16; o; o >>= 1) {
        wm = fmaxf(wm, __shfl_xor_sync(0xffffffffu, wm, o));
        ls += __shfl_xor_sync(0xffffffffu, ls, o);
    }
    ls = fmaxf(ls, 1e-37f);
    if (lane == 0) outh[row] = logw - (shift + __logf(ls));
    shift = wm + 1.0f;
}

__global__ void __launch_bounds__(256, 2) sparse_multi_kernel(
        const __nv_bfloat16* __restrict__ S, const __nv_bfloat16* __restrict__ St,
        float* __restrict__ fh, float* __restrict__ gh,
        float* __restrict__ mf, float* __restrict__ mg,
        const unsigned short* __restrict__ idxf, const int* __restrict__ cntf,
        const unsigned short* __restrict__ idxg, const int* __restrict__ cntg,
        int niter) {
    int tid = threadIdx.x, warp = tid >> 5, lane = tid & 31;
    int gw = blockIdx.x * 8 + warp;          /* 0..2047 */
    int r0 = gw, r1 = gw + 2048;
    float sf0 = mf[r0], sf1 = mf[r1];
    float sg0 = mg[r0], sg1 = mg[r1];
    int cf0 = cntf[r0], cf1 = cntf[r1];
    int cg0 = cntg[r0], cg1 = cntg[r1];

    for (int it = 0; it < niter; ++it) {
        sparse_row(S, gh, fh, idxf, cf0, r0, sf0, LA, lane);
        sparse_row(S, gh, fh, idxf, cf1, r1, sf1, LA, lane);
        grid_barrier();
        sparse_row(St, fh, gh, idxg, cg0, r0, sg0, LB, lane);
        sparse_row(St, fh, gh, idxg, cg1, r1, sg1, LB, lane);
        grid_barrier();
    }
    if (lane == 0) {
        mf[r0] = sf0; mf[r1] = sf1;
        mg[r0] = sg0; mg[r1] = sg1;
    }
}

/* ======= exact P row/col sums (final) ======= */
__global__ void __launch_bounds__(256) psum_kernel(const uint4* __restrict__ S,
                                                   const float* __restrict__ vh,
                                                   const float* __restrict__ scalh,
                                                   float* __restrict__ outv) {
    __shared__ float gs[N];
    __shared__ float redS[8];
    int tid = threadIdx.x;
#pragma unroll
    for (int c = 0; c < 4; ++c)
        ((float4*)gs)[tid + c * 256] = ((const float4*)vh)[tid + c * 256];
    __syncthreads();
    int warp = tid >> 5, lane = tid & 31;

    for (int r = 0; r < RPB; ++r) {
        int row = blockIdx.x * RPB + r;
        float fr = scalh[row];
        const uint4* Sr = S + (size_t)row * (N / 8);
        float ls = 0.f;
#pragma unroll
        for (int c = 0; c < 2; ++c) {
            int idx = tid + c * 256;
            uint4 u = Sr[idx];
            float sv[8];
            unpack8(u, sv);
            float4 gA = ((const float4*)gs)[2 * idx];
            float4 gB = ((const float4*)gs)[2 * idx + 1];
            float t[8];
            t[0] = fr + gA.x + sv[0]; t[1] = fr + gA.y + sv[1];
            t[2] = fr + gA.z + sv[2]; t[3] = fr + gA.w + sv[3];
            t[4] = fr + gB.x + sv[4]; t[5] = fr + gB.y + sv[5];
            t[6] = fr + gB.z + sv[6]; t[7] = fr + gB.w + sv[7];
#pragma unroll
            for (int k = 0; k < 8; ++k)
                if (t[k] > THRESH_P) ls += __expf(t[k]);
        }
#pragma unroll
        for (int o = 16; o; o >>= 1) ls += __shfl_xor_sync(0xffffffffu, ls, o);
        if (lane == 0) redS[warp] = ls;
        __syncthreads();
        if (tid == 0) {
            float s = redS[0];
#pragma unroll
            for (int k = 1; k < 8; ++k) s += redS[k];
            outv[row] = s;
        }
        __syncthreads();
    }
}

/* loss = sum_i f_i R_i + sum_j g_j C_j - (la+lb+1) * sum R + 1 */
__global__ void __launch_bounds__(256) final_kernel(float* __restrict__ out) {
    int tid = threadIdx.x;
    double acc = 0.0;
    const double k = (double)LA + (double)LB + 1.0;
    for (int i = tid; i < N; i += 256) {
        double Ri = (double)d_R[i];
        double fi = (double)d_fh[i] + (double)d_x2[i];
        double gi = (double)d_gh[i] + (double)d_y2[i];
        acc += fi * Ri + gi * (double)d_C[i] - k * Ri;
    }
    __shared__ double red[256];
    red[tid] = acc;
    __syncthreads();
    for (int o = 128; o; o >>= 1) {
        if (tid < o) red[tid] += red[tid + o];
        __syncthreads();
    }
    if (tid == 0) out[0] = (float)(red[0] + 1.0);
}

/* ================================================================= */
extern "C" void kernel_launch(void* const* d_in, const int* in_sizes, int n_in,
                              void* d_out, int out_size) {
    (void)in_sizes; (void)n_in; (void)out_size;
    const float* x = (const float*)d_in[0];
    const float* y = (const float*)d_in[1];
    float* out = (float*)d_out;

    void *pS_, *pSt_, *pfh_, *pgh_, *pmf_, *pmg_, *pR_, *pC_;
    void *pif_, *pig_, *pcf_, *pcg_;
    cudaGetSymbolAddress(&pS_,  d_S);
    cudaGetSymbolAddress(&pSt_, d_St);
    cudaGetSymbolAddress(&pfh_, d_fh);
    cudaGetSymbolAddress(&pgh_, d_gh);
    cudaGetSymbolAddress(&pmf_, d_mf);
    cudaGetSymbolAddress(&pmg_, d_mg);
    cudaGetSymbolAddress(&pR_,  d_R);
    cudaGetSymbolAddress(&pC_,  d_C);
    cudaGetSymbolAddress(&pif_, d_idxf);
    cudaGetSymbolAddress(&pig_, d_idxg);
    cudaGetSymbolAddress(&pcf_, d_cntf);
    cudaGetSymbolAddress(&pcg_, d_cntg);
    const uint4* pS  = (const uint4*)pS_;
    const uint4* pSt = (const uint4*)pSt_;
    const __nv_bfloat16* pSb  = (const __nv_bfloat16*)pS_;
    const __nv_bfloat16* pStb = (const __nv_bfloat16*)pSt_;
    float* pfh = (float*)pfh_;
    float* pgh = (float*)pgh_;
    float* pmf = (float*)pmf_;
    float* pmg = (float*)pmg_;
    float* pR  = (float*)pR_;
    float* pC  = (float*)pC_;
    unsigned short* pif = (unsigned short*)pif_;
    unsigned short* pig = (unsigned short*)pig_;
    int* pcf = (int*)pcf_;
    int* pcg = (int*)pcg_;

    prep_kernel<<<1024, 256>>>(x, y);
    gemm_tc_kernel<<<dim3(32, 32), 256>>>();

    /* 4 exact seed iterations */
    for (int it = 0; it < 4; ++it) {
        lse_kernel<<<N / RPB, 256>>>(pS,  pgh, pfh, pmf, LA);
        lse_kernel<<<N / RPB, 256>>>(pSt, pfh, pgh, pmg, LB);
    }

    /* rebuild at {4,8,16,32,48,64,80,96}; persistent sparse segments between */
    const int rbs[8]  = {4, 8, 16, 32, 48, 64, 80, 96};
    const int segs[8] = {3, 7, 15, 15, 15, 15, 15, 3};   /* sparse iters after each rebuild */
    for (int s = 0; s < 8; ++s) {
        (void)rbs;
        lse_rebuild_kernel<<<N / 8, 256>>>(pS,  pgh, pfh, pmf, pif, pcf, LA);
        lse_rebuild_kernel<<<N / 8, 256>>>(pSt, pfh, pgh, pmg, pig, pcg, LB);
        sparse_multi_kernel<<<PBLK, 256>>>(pSb, pStb, pfh, pgh, pmf, pmg,
                                           pif, pcf, pig, pcg, segs[s]);
    }

    psum_kernel<<<N / RPB, 256>>>(pS,  pgh, pfh, pR);
    psum_kernel<<<N / RPB, 256>>>(pSt, pfh, pgh, pC);
    final_kernel<<<1, 256>>>(out);
}